// round 11
// baseline (speedup 1.0000x reference)
#include <cuda_runtime.h>
#include <cuda_bf16.h>
#include <cuda_fp16.h>
#include <cstdint>

#define KIN 512
#define NH  128
#define N_MAX 100000
#define E_MAX 1600000
#define SCAN_B 256
#define NB_MAX ((N_MAX + SCAN_B - 1) / SCAN_B)

// ---------------- scratch (no allocations allowed) ----------------
__device__ __half g_hh[(size_t)N_MAX * NH];    // h = x @ W  (fp16)
__device__ int   g_deg_in [N_MAX];
__device__ int   g_deg_out[N_MAX];
__device__ float g_norm_out[N_MAX];
__device__ float g_norm_in [N_MAX];
__device__ int   g_row  [N_MAX];
__device__ int   g_cur  [N_MAX];
__device__ int   g_csrc [E_MAX];
__device__ int   g_part [NB_MAX];
__device__ int   g_poff [NB_MAX];
__device__ float g_wsum[NH];
__device__ float g_bsum;
__device__ __half g_bhi[NH * KIN];             // W^T fp16 hi : [n][k]
__device__ __half g_blo[NH * KIN];             // W^T fp16 lo : [n][k]

// ================= helpers =================
__device__ __forceinline__ uint32_t smem_u32(const void* p) {
    uint32_t a;
    asm("{ .reg .u64 t; cvta.to.shared.u64 t, %1; cvt.u32.u64 %0, t; }"
        : "=r"(a) : "l"(p));
    return a;
}

__device__ __forceinline__ void ldsm4(uint32_t* r, uint32_t addr) {
    asm volatile("ldmatrix.sync.aligned.m8n8.x4.shared.b16 {%0,%1,%2,%3}, [%4];"
                 : "=r"(r[0]), "=r"(r[1]), "=r"(r[2]), "=r"(r[3]) : "r"(addr));
}

__device__ __forceinline__ void mma_f16(float* d, const uint32_t* a, const uint32_t* b) {
    asm volatile(
        "mma.sync.aligned.m16n8k16.row.col.f32.f16.f16.f32 "
        "{%0,%1,%2,%3}, {%4,%5,%6,%7}, {%8,%9}, {%0,%1,%2,%3};"
        : "+f"(d[0]), "+f"(d[1]), "+f"(d[2]), "+f"(d[3])
        : "r"(a[0]), "r"(a[1]), "r"(a[2]), "r"(a[3]), "r"(b[0]), "r"(b[1]));
}

#define CP16(dst, src) \
    asm volatile("cp.async.cg.shared.global [%0], [%1], 16;" :: "r"(dst), "l"(src))
#define CP_COMMIT() asm volatile("cp.async.commit_group;" ::: "memory")
#define CP_WAIT0()  asm volatile("cp.async.wait_group 0;"  ::: "memory")
#define STS128(a, r0, r1, r2, r3) \
    asm volatile("st.shared.v4.b32 [%0], {%1,%2,%3,%4};" \
                 :: "r"(a), "r"(r0), "r"(r1), "r"(r2), "r"(r3))

// ---------------- zero small scratch ----------------
__global__ void zero_kernel(int N) {
    int i = blockIdx.x * blockDim.x + threadIdx.x;
    if (i < N) { g_deg_in[i] = 0; g_deg_out[i] = 0; }
}

// ---------------- degree counting ----------------
__global__ void degree_kernel(const int* __restrict__ src,
                              const int* __restrict__ dst, int E) {
    int i = blockIdx.x * blockDim.x + threadIdx.x;
    if (i < E) {
        atomicAdd(&g_deg_out[src[i]], 1);
        atomicAdd(&g_deg_in [dst[i]], 1);
    }
}

// ---------------- W transpose + fp16 split: g_bhi/g_blo[n][k] ----------------
__global__ void wsplit_kernel(const float* __restrict__ W) {
    int i = blockIdx.x * blockDim.x + threadIdx.x;
    if (i < KIN * NH) {
        int k = i >> 7, n = i & 127;
        float v = W[i];
        __half h = __float2half_rn(v);
        float l = v - __half2float(h);
        g_bhi[n * KIN + k] = h;
        g_blo[n * KIN + k] = __float2half_rn(l);
    }
}

// ---------------- scans ----------------
__global__ void scan1_kernel(int N) {
    __shared__ int s[SCAN_B];
    int t = threadIdx.x;
    int i = blockIdx.x * SCAN_B + t;
    int v = (i < N) ? g_deg_in[i] : 0;
    s[t] = v;
    __syncthreads();
    int acc = v;
    #pragma unroll
    for (int o = 1; o < SCAN_B; o <<= 1) {
        int add = (t >= o) ? s[t - o] : 0;
        __syncthreads();
        acc += add;
        s[t] = acc;
        __syncthreads();
    }
    if (i < N) g_row[i] = acc - v;
    if (t == SCAN_B - 1) g_part[blockIdx.x] = acc;
}

__global__ void scan2_kernel(int nb) {
    __shared__ int s[512];
    int t = threadIdx.x;
    int v = (t < nb) ? g_part[t] : 0;
    s[t] = v;
    __syncthreads();
    int acc = v;
    #pragma unroll
    for (int o = 1; o < 512; o <<= 1) {
        int add = (t >= o) ? s[t - o] : 0;
        __syncthreads();
        acc += add;
        s[t] = acc;
        __syncthreads();
    }
    if (t < nb) g_poff[t] = acc - v;
}

// scan3 + norm fused
__global__ void scan3_kernel(int N) {
    int i = blockIdx.x * SCAN_B + threadIdx.x;
    if (i < N) {
        int r = g_row[i] + g_poff[blockIdx.x];
        g_row[i] = r;
        g_cur[i] = r;          // fill cursor starts at row offset
        g_norm_out[i] = rsqrtf(fmaxf((float)g_deg_out[i], 1.0f));
        g_norm_in[i]  = rsqrtf(fmaxf((float)g_deg_in[i],  1.0f));
    }
}

// ---------------- CSR fill ----------------
__global__ void fill_kernel(const int* __restrict__ src,
                            const int* __restrict__ dst, int E) {
    int i = blockIdx.x * blockDim.x + threadIdx.x;
    if (i < E) {
        int d = dst[i];
        int pos = atomicAdd(&g_cur[d], 1);
        g_csrc[pos] = src[i];
    }
}

// ---------------- wsum + bsum fused ----------------
__global__ void wsum_kernel(const float* __restrict__ mlpW,
                            const float* __restrict__ mlpb) {
    int j = blockIdx.x;
    int lane = threadIdx.x;
    float s = 0.f;
    if (j < NH) {
        #pragma unroll
        for (int k = lane; k < NH; k += 32) s += mlpW[j * NH + k];
        #pragma unroll
        for (int o = 16; o > 0; o >>= 1) s += __shfl_xor_sync(0xFFFFFFFFu, s, o);
        if (lane == 0) g_wsum[j] = s;
    } else {
        #pragma unroll
        for (int k = lane; k < NH; k += 32) s += mlpb[k];
        #pragma unroll
        for (int o = 16; o > 0; o >>= 1) s += __shfl_xor_sync(0xFFFFFFFFu, s, o);
        if (lane == 0) g_bsum = s;
    }
}

// ============ fp16 HMMA GEMM (A single, W split), 64x128 tile, A dist-2 ============
// acc = A·Whi + A·Wlo  (A = fp16(x), rounding ~2^-12)
#define PAD 40           // fp16 elems per SMEM row (80B)
#define OFF_BHI 5120     // A: 64 rows x 80B
#define OFF_BLO 15360    // Bhi: 128 rows x 80B
#define STAGE_B 25600
#define GEMM_SMEM (2 * STAGE_B)
#define NKT (KIN / 32)   // 16 K-tiles

__global__ __launch_bounds__(256, 3) void gemm_mma_kernel(const float* __restrict__ A, int M) {
    extern __shared__ char smem[];
    uint32_t sb = smem_u32(smem);

    int tid = threadIdx.x;
    int lane = tid & 31, wid = tid >> 5;
    int wm = wid & 1;       // 2 m-slabs of 32
    int wn = wid >> 1;      // 4 n-slabs of 32
    int row0 = blockIdx.x * 64;

    float acc[2][4][4];
    #pragma unroll
    for (int i = 0; i < 2; i++)
        #pragma unroll
        for (int j = 0; j < 4; j++)
            #pragma unroll
            for (int q = 0; q < 4; q++) acc[i][j][q] = 0.f;

    int lr = tid >> 2;           // row within A tile (0..63)
    int lq = tid & 3;            // 8-float chunk (0..3)
    bool avalid = (row0 + lr) < M;
    const float* aptr = A + (size_t)(row0 + lr) * KIN + lq * 8;
    int br0 = tid >> 2;          // B row base (0..63)
    int bpart = (tid & 3) * 16;  // 16B part within 64B row

    float fA[2][8];
    // ---- prologue: A(0), A(1) regs + B(0) cp.async ----
    if (avalid) {
        const float4* p0 = (const float4*)aptr;
        *(float4*)(fA[0])     = p0[0];
        *(float4*)(fA[0] + 4) = p0[1];
        const float4* p1 = (const float4*)(aptr + 32);
        *(float4*)(fA[1])     = p1[0];
        *(float4*)(fA[1] + 4) = p1[1];
    } else {
        #pragma unroll
        for (int i = 0; i < 8; i++) { fA[0][i] = 0.f; fA[1][i] = 0.f; }
    }
    #pragma unroll
    for (int i = 0; i < 2; i++) {
        int r = br0 + i * 64;
        uint32_t d = sb + OFF_BHI + (uint32_t)r * 80 + bpart;
        CP16(d, (const char*)(g_bhi + (size_t)r * KIN) + bpart);
        CP16(d + (OFF_BLO - OFF_BHI), (const char*)(g_blo + (size_t)r * KIN) + bpart);
    }
    CP_COMMIT();

    #pragma unroll 1
    for (int t = 0; t < NKT; t++) {
        uint32_t base = sb + (uint32_t)(t & 1) * STAGE_B;
        int buf = t & 1;

        // ---- convert & store A(t): single fp16, one 16B store ----
        uint32_t hi[4];
        #pragma unroll
        for (int p = 0; p < 4; p++) {
            __half2 h2 = __floats2half2_rn(fA[buf][2 * p], fA[buf][2 * p + 1]);
            hi[p] = *(uint32_t*)&h2;
        }
        uint32_t adst = base + (uint32_t)lr * 80 + (uint32_t)lq * 16;
        STS128(adst, hi[0], hi[1], hi[2], hi[3]);

        CP_WAIT0();          // B(t) arrived (only pending group)
        __syncthreads();     // stage safe for writes below; tile t-1 compute done

        // ---- prefetch A(t+2) into the buffer just consumed ----
        if (t + 2 < NKT && avalid) {
            const float4* p = (const float4*)(aptr + (t + 2) * 32);
            *(float4*)(fA[buf])     = p[0];
            *(float4*)(fA[buf] + 4) = p[1];
        }
        // ---- prefetch B(t+1) into other stage ----
        if (t + 1 < NKT) {
            int k0n = (t + 1) * 32;
            uint32_t nbase = sb + (uint32_t)((t + 1) & 1) * STAGE_B;
            #pragma unroll
            for (int i = 0; i < 2; i++) {
                int r = br0 + i * 64;
                uint32_t d = nbase + OFF_BHI + (uint32_t)r * 80 + bpart;
                CP16(d, (const char*)(g_bhi + (size_t)r * KIN + k0n) + bpart);
                CP16(d + (OFF_BLO - OFF_BHI),
                     (const char*)(g_blo + (size_t)r * KIN + k0n) + bpart);
            }
            CP_COMMIT();
        }

        // ---- compute tile t: 2 passes (Bhi, Blo) ----
        #pragma unroll
        for (int kk = 0; kk < 2; kk++) {
            int kc = kk * 16 + ((lane >> 4) << 3);
            int arow = wm * 32 + (lane & 15);
            uint32_t ah[2][4];
            #pragma unroll
            for (int mi = 0; mi < 2; mi++) {
                uint32_t addr = base + (uint32_t)((arow + mi * 16) * PAD + kc) * 2;
                ldsm4(ah[mi], addr);
            }
            int brow = wn * 32 + (lane & 15);
            uint32_t bh[4][2], bl[4][2];
            #pragma unroll
            for (int np = 0; np < 2; np++) {
                uint32_t r[4];
                uint32_t addr = base + OFF_BHI + (uint32_t)((brow + np * 16) * PAD + kc) * 2;
                ldsm4(r, addr);
                bh[2 * np][0] = r[0]; bh[2 * np][1] = r[2];
                bh[2 * np + 1][0] = r[1]; bh[2 * np + 1][1] = r[3];
                ldsm4(r, addr + (OFF_BLO - OFF_BHI));
                bl[2 * np][0] = r[0]; bl[2 * np][1] = r[2];
                bl[2 * np + 1][0] = r[1]; bl[2 * np + 1][1] = r[3];
            }
            #pragma unroll
            for (int mi = 0; mi < 2; mi++)
                #pragma unroll
                for (int ni = 0; ni < 4; ni++) {
                    mma_f16(acc[mi][ni], ah[mi], bh[ni]);
                    mma_f16(acc[mi][ni], ah[mi], bl[ni]);
                }
        }
    }

    int r = lane >> 2, c = (lane & 3) * 2;
    #pragma unroll
    for (int mi = 0; mi < 2; mi++) {
        int m0 = row0 + wm * 32 + mi * 16 + r;
        #pragma unroll
        for (int ni = 0; ni < 4; ni++) {
            int n = wn * 32 + ni * 8 + c;
            if (m0 < M) {
                __half2 v = __floats2half2_rn(acc[mi][ni][0], acc[mi][ni][1]);
                *(__half2*)&g_hh[(size_t)m0 * NH + n] = v;
            }
            if (m0 + 8 < M) {
                __half2 v = __floats2half2_rn(acc[mi][ni][2], acc[mi][ni][3]);
                *(__half2*)&g_hh[(size_t)(m0 + 8) * NH + n] = v;
            }
        }
    }
}

// ---------------- fused gather + finalize: one warp per dst node (fp16 h) ----------------
__global__ void gather_kernel(const int* __restrict__ perm,
                              const float* __restrict__ b,
                              const float* __restrict__ alpha,
                              float* __restrict__ out, int N) {
    size_t gid = (size_t)blockIdx.x * blockDim.x + threadIdx.x;
    int node = (int)(gid >> 5);
    int lane = (int)(gid & 31);
    if (node >= N) return;

    int start = g_row[node];
    int cnt   = g_deg_in[node];

    float4 acc1 = make_float4(0.f, 0.f, 0.f, 0.f);
    float4 acc2 = make_float4(0.f, 0.f, 0.f, 0.f);

    for (int i = 0; i < cnt; i++) {
        int s  = __ldg(&g_csrc[start + i]);
        int sp = __ldg(&perm[s]);
        float sc = __ldg(&g_norm_out[s]);
        uint2 u1 = *(const uint2*)(g_hh + (size_t)s  * NH + lane * 4);
        uint2 u2 = *(const uint2*)(g_hh + (size_t)sp * NH + lane * 4);
        float2 a = __half22float2(*(__half2*)&u1.x);
        float2 bq = __half22float2(*(__half2*)&u1.y);
        float2 cq = __half22float2(*(__half2*)&u2.x);
        float2 d = __half22float2(*(__half2*)&u2.y);
        acc1.x = fmaf(a.x,  sc, acc1.x);
        acc1.y = fmaf(a.y,  sc, acc1.y);
        acc1.z = fmaf(bq.x, sc, acc1.z);
        acc1.w = fmaf(bq.y, sc, acc1.w);
        acc2.x = fmaf(cq.x, sc, acc2.x);
        acc2.y = fmaf(cq.y, sc, acc2.y);
        acc2.z = fmaf(d.x,  sc, acc2.z);
        acc2.w = fmaf(d.y,  sc, acc2.w);
    }

    float nin = g_norm_in[node];
    float4 bb = *(const float4*)(b      + lane * 4);
    float4 al = *(const float4*)(alpha  + lane * 4);
    float4 ws = *(const float4*)(g_wsum + lane * 4);

    float r1 = 0.f, r2 = 0.f, v;
    v = acc1.x * nin + bb.x; v = (v >= 0.f) ? v : al.x * v; r1 += v * ws.x;
    v = acc1.y * nin + bb.y; v = (v >= 0.f) ? v : al.y * v; r1 += v * ws.y;
    v = acc1.z * nin + bb.z; v = (v >= 0.f) ? v : al.z * v; r1 += v * ws.z;
    v = acc1.w * nin + bb.w; v = (v >= 0.f) ? v : al.w * v; r1 += v * ws.w;
    v = acc2.x * nin + bb.x; v = (v >= 0.f) ? v : al.x * v; r2 += v * ws.x;
    v = acc2.y * nin + bb.y; v = (v >= 0.f) ? v : al.y * v; r2 += v * ws.y;
    v = acc2.z * nin + bb.z; v = (v >= 0.f) ? v : al.z * v; r2 += v * ws.z;
    v = acc2.w * nin + bb.w; v = (v >= 0.f) ? v : al.w * v; r2 += v * ws.w;

    #pragma unroll
    for (int o = 16; o > 0; o >>= 1) {
        r1 += __shfl_xor_sync(0xFFFFFFFFu, r1, o);
        r2 += __shfl_xor_sync(0xFFFFFFFFu, r2, o);
    }
    if (lane == 0) {
        float bs = g_bsum;
        out[node]     = r1 + bs;
        out[N + node] = r2 + bs;
    }
}

// ---------------- launch ----------------
extern "C" void kernel_launch(void* const* d_in, const int* in_sizes, int n_in,
                              void* d_out, int out_size) {
    const float* x     = (const float*)d_in[0];
    const int*   src   = (const int*)  d_in[1];
    const int*   dst   = (const int*)  d_in[2];
    const int*   perm  = (const int*)  d_in[3];
    const float* W     = (const float*)d_in[4];
    const float* b     = (const float*)d_in[5];
    const float* alpha = (const float*)d_in[6];
    const float* mlpW  = (const float*)d_in[7];
    const float* mlpb  = (const float*)d_in[8];
    float* out = (float*)d_out;

    int E = in_sizes[1];
    int N = in_sizes[3];
    if (N > N_MAX || E > E_MAX) return;

    int nb = (N + SCAN_B - 1) / SCAN_B;

    cudaFuncSetAttribute(gemm_mma_kernel,
                         cudaFuncAttributeMaxDynamicSharedMemorySize, GEMM_SMEM);

    zero_kernel   <<<(N + 255) / 256, 256>>>(N);
    degree_kernel <<<(E + 255) / 256, 256>>>(src, dst, E);
    wsplit_kernel <<<(KIN * NH + 255) / 256, 256>>>(W);
    gemm_mma_kernel<<<(N + 63) / 64, 256, GEMM_SMEM>>>(x, N);   // launch index 3 (ncu target)
    scan1_kernel  <<<nb, SCAN_B>>>(N);
    scan2_kernel  <<<1, 512>>>(nb);
    scan3_kernel  <<<nb, SCAN_B>>>(N);
    fill_kernel   <<<(E + 255) / 256, 256>>>(src, dst, E);
    wsum_kernel   <<<NH + 1, 32>>>(mlpW, mlpb);

    size_t gthreads = (size_t)N * 32;
    gather_kernel<<<(unsigned)((gthreads + 255) / 256), 256>>>(perm, b, alpha, out, N);
}

// round 12
// speedup vs baseline: 1.0403x; 1.0403x over previous
#include <cuda_runtime.h>
#include <cuda_bf16.h>
#include <cuda_fp16.h>
#include <cstdint>

#define KIN 512
#define NH  128
#define N_MAX 100000
#define E_MAX 1600000
#define SCAN_B 256
#define NB_MAX ((N_MAX + SCAN_B - 1) / SCAN_B)

// ---------------- scratch (no allocations allowed) ----------------
__device__ __half g_hh[(size_t)N_MAX * NH];    // h = x @ W  (fp16)
__device__ int   g_deg_in [N_MAX];
__device__ int   g_deg_out[N_MAX];
__device__ float g_norm_out[N_MAX];
__device__ float g_norm_in [N_MAX];
__device__ int   g_row  [N_MAX];
__device__ int   g_cur  [N_MAX];
__device__ int   g_csrc [E_MAX];
__device__ int   g_part [NB_MAX];
__device__ int   g_poff [NB_MAX];
__device__ float g_wsum[NH];
__device__ float g_bsum;
__device__ __half g_bhi[NH * KIN];             // W^T fp16 hi : [n][k]
__device__ __half g_blo[NH * KIN];             // W^T fp16 lo : [n][k]

// ================= helpers =================
__device__ __forceinline__ uint32_t smem_u32(const void* p) {
    uint32_t a;
    asm("{ .reg .u64 t; cvta.to.shared.u64 t, %1; cvt.u32.u64 %0, t; }"
        : "=r"(a) : "l"(p));
    return a;
}

__device__ __forceinline__ void ldsm4(uint32_t* r, uint32_t addr) {
    asm volatile("ldmatrix.sync.aligned.m8n8.x4.shared.b16 {%0,%1,%2,%3}, [%4];"
                 : "=r"(r[0]), "=r"(r[1]), "=r"(r[2]), "=r"(r[3]) : "r"(addr));
}

__device__ __forceinline__ void mma_f16(float* d, const uint32_t* a, const uint32_t* b) {
    asm volatile(
        "mma.sync.aligned.m16n8k16.row.col.f32.f16.f16.f32 "
        "{%0,%1,%2,%3}, {%4,%5,%6,%7}, {%8,%9}, {%0,%1,%2,%3};"
        : "+f"(d[0]), "+f"(d[1]), "+f"(d[2]), "+f"(d[3])
        : "r"(a[0]), "r"(a[1]), "r"(a[2]), "r"(a[3]), "r"(b[0]), "r"(b[1]));
}

#define CP16(dst, src) \
    asm volatile("cp.async.cg.shared.global [%0], [%1], 16;" :: "r"(dst), "l"(src))
#define CP_COMMIT() asm volatile("cp.async.commit_group;" ::: "memory")
#define CP_WAIT0()  asm volatile("cp.async.wait_group 0;"  ::: "memory")
#define STS128(a, r0, r1, r2, r3) \
    asm volatile("st.shared.v4.b32 [%0], {%1,%2,%3,%4};" \
                 :: "r"(a), "r"(r0), "r"(r1), "r"(r2), "r"(r3))

// ---------------- zero small scratch ----------------
__global__ void zero_kernel(int N) {
    int i = blockIdx.x * blockDim.x + threadIdx.x;
    if (i < N) { g_deg_in[i] = 0; g_deg_out[i] = 0; }
}

// ---------------- degree counting ----------------
__global__ void degree_kernel(const int* __restrict__ src,
                              const int* __restrict__ dst, int E) {
    int i = blockIdx.x * blockDim.x + threadIdx.x;
    if (i < E) {
        atomicAdd(&g_deg_out[src[i]], 1);
        atomicAdd(&g_deg_in [dst[i]], 1);
    }
}

// ---------------- W transpose + fp16 split: g_bhi/g_blo[n][k] ----------------
__global__ void wsplit_kernel(const float* __restrict__ W) {
    int i = blockIdx.x * blockDim.x + threadIdx.x;
    if (i < KIN * NH) {
        int k = i >> 7, n = i & 127;
        float v = W[i];
        __half h = __float2half_rn(v);
        float l = v - __half2float(h);
        g_bhi[n * KIN + k] = h;
        g_blo[n * KIN + k] = __float2half_rn(l);
    }
}

// ---------------- scans ----------------
__global__ void scan1_kernel(int N) {
    __shared__ int s[SCAN_B];
    int t = threadIdx.x;
    int i = blockIdx.x * SCAN_B + t;
    int v = (i < N) ? g_deg_in[i] : 0;
    s[t] = v;
    __syncthreads();
    int acc = v;
    #pragma unroll
    for (int o = 1; o < SCAN_B; o <<= 1) {
        int add = (t >= o) ? s[t - o] : 0;
        __syncthreads();
        acc += add;
        s[t] = acc;
        __syncthreads();
    }
    if (i < N) g_row[i] = acc - v;
    if (t == SCAN_B - 1) g_part[blockIdx.x] = acc;
}

__global__ void scan2_kernel(int nb) {
    __shared__ int s[512];
    int t = threadIdx.x;
    int v = (t < nb) ? g_part[t] : 0;
    s[t] = v;
    __syncthreads();
    int acc = v;
    #pragma unroll
    for (int o = 1; o < 512; o <<= 1) {
        int add = (t >= o) ? s[t - o] : 0;
        __syncthreads();
        acc += add;
        s[t] = acc;
        __syncthreads();
    }
    if (t < nb) g_poff[t] = acc - v;
}

// scan3 + norm fused
__global__ void scan3_kernel(int N) {
    int i = blockIdx.x * SCAN_B + threadIdx.x;
    if (i < N) {
        int r = g_row[i] + g_poff[blockIdx.x];
        g_row[i] = r;
        g_cur[i] = r;          // fill cursor starts at row offset
        g_norm_out[i] = rsqrtf(fmaxf((float)g_deg_out[i], 1.0f));
        g_norm_in[i]  = rsqrtf(fmaxf((float)g_deg_in[i],  1.0f));
    }
}

// ---------------- CSR fill ----------------
__global__ void fill_kernel(const int* __restrict__ src,
                            const int* __restrict__ dst, int E) {
    int i = blockIdx.x * blockDim.x + threadIdx.x;
    if (i < E) {
        int d = dst[i];
        int pos = atomicAdd(&g_cur[d], 1);
        g_csrc[pos] = src[i];
    }
}

// ---------------- wsum + bsum fused ----------------
__global__ void wsum_kernel(const float* __restrict__ mlpW,
                            const float* __restrict__ mlpb) {
    int j = blockIdx.x;
    int lane = threadIdx.x;
    float s = 0.f;
    if (j < NH) {
        #pragma unroll
        for (int k = lane; k < NH; k += 32) s += mlpW[j * NH + k];
        #pragma unroll
        for (int o = 16; o > 0; o >>= 1) s += __shfl_xor_sync(0xFFFFFFFFu, s, o);
        if (lane == 0) g_wsum[j] = s;
    } else {
        #pragma unroll
        for (int k = lane; k < NH; k += 32) s += mlpb[k];
        #pragma unroll
        for (int o = 16; o > 0; o >>= 1) s += __shfl_xor_sync(0xFFFFFFFFu, s, o);
        if (lane == 0) g_bsum = s;
    }
}

// ============ fp16 HMMA GEMM (A single, W split), 64x128 tile ============
// A-prefetch distance 2 with STATIC register buffers (manual unroll-by-2).
// acc = A·Whi + A·Wlo  (A = fp16(x), rounding ~2^-12)
#define PAD 40           // fp16 elems per SMEM row (80B)
#define OFF_BHI 5120     // A: 64 rows x 80B
#define OFF_BLO 15360    // Bhi: 128 rows x 80B
#define STAGE_B 25600
#define GEMM_SMEM (2 * STAGE_B)
#define NKT (KIN / 32)   // 16 K-tiles (even)

// one pipeline body; T runtime tile index, STAGE compile-time 0/1, FA static array
#define GEMM_BODY(T, STAGE, FA)                                               \
{                                                                             \
    const uint32_t base = sb + (uint32_t)(STAGE) * STAGE_B;                   \
    uint32_t hi[4];                                                           \
    _Pragma("unroll")                                                         \
    for (int p = 0; p < 4; p++) {                                             \
        __half2 h2 = __floats2half2_rn((FA)[2 * p], (FA)[2 * p + 1]);         \
        hi[p] = *(uint32_t*)&h2;                                              \
    }                                                                         \
    uint32_t adst = base + (uint32_t)lr * 80 + (uint32_t)lq * 16;             \
    STS128(adst, hi[0], hi[1], hi[2], hi[3]);                                 \
    CP_WAIT0();                                                               \
    __syncthreads();                                                          \
    if ((T) + 2 < NKT && avalid) {                                            \
        const float4* p = (const float4*)(aptr + ((T) + 2) * 32);             \
        *(float4*)(FA)     = p[0];                                            \
        *(float4*)((FA)+4) = p[1];                                            \
    }                                                                         \
    if ((T) + 1 < NKT) {                                                      \
        int k0n = ((T) + 1) * 32;                                             \
        uint32_t nbase = sb + (uint32_t)(1 - (STAGE)) * STAGE_B;              \
        _Pragma("unroll")                                                     \
        for (int i = 0; i < 2; i++) {                                         \
            int rr = br0 + i * 64;                                            \
            uint32_t d = nbase + OFF_BHI + (uint32_t)rr * 80 + bpart;         \
            CP16(d, (const char*)(g_bhi + (size_t)rr * KIN + k0n) + bpart);   \
            CP16(d + (OFF_BLO - OFF_BHI),                                     \
                 (const char*)(g_blo + (size_t)rr * KIN + k0n) + bpart);      \
        }                                                                     \
        CP_COMMIT();                                                          \
    }                                                                         \
    _Pragma("unroll")                                                         \
    for (int kk = 0; kk < 2; kk++) {                                          \
        int kc = kk * 16 + ((lane >> 4) << 3);                                \
        int arow = wm * 32 + (lane & 15);                                     \
        uint32_t ah[2][4];                                                    \
        _Pragma("unroll")                                                     \
        for (int mi = 0; mi < 2; mi++) {                                      \
            uint32_t addr = base + (uint32_t)((arow + mi * 16) * PAD + kc) * 2;\
            ldsm4(ah[mi], addr);                                              \
        }                                                                     \
        int brow = wn * 32 + (lane & 15);                                     \
        uint32_t bh[4][2], bl[4][2];                                          \
        _Pragma("unroll")                                                     \
        for (int np = 0; np < 2; np++) {                                      \
            uint32_t rg[4];                                                   \
            uint32_t addr = base + OFF_BHI + (uint32_t)((brow + np * 16) * PAD + kc) * 2;\
            ldsm4(rg, addr);                                                  \
            bh[2 * np][0] = rg[0]; bh[2 * np][1] = rg[2];                     \
            bh[2 * np + 1][0] = rg[1]; bh[2 * np + 1][1] = rg[3];             \
            ldsm4(rg, addr + (OFF_BLO - OFF_BHI));                            \
            bl[2 * np][0] = rg[0]; bl[2 * np][1] = rg[2];                     \
            bl[2 * np + 1][0] = rg[1]; bl[2 * np + 1][1] = rg[3];             \
        }                                                                     \
        _Pragma("unroll")                                                     \
        for (int mi = 0; mi < 2; mi++)                                        \
            _Pragma("unroll")                                                 \
            for (int ni = 0; ni < 4; ni++) {                                  \
                mma_f16(acc[mi][ni], ah[mi], bh[ni]);                         \
                mma_f16(acc[mi][ni], ah[mi], bl[ni]);                         \
            }                                                                 \
    }                                                                         \
}

__global__ __launch_bounds__(256, 3) void gemm_mma_kernel(const float* __restrict__ A, int M) {
    extern __shared__ char smem[];
    uint32_t sb = smem_u32(smem);

    int tid = threadIdx.x;
    int lane = tid & 31, wid = tid >> 5;
    int wm = wid & 1;       // 2 m-slabs of 32
    int wn = wid >> 1;      // 4 n-slabs of 32
    int row0 = blockIdx.x * 64;

    float acc[2][4][4];
    #pragma unroll
    for (int i = 0; i < 2; i++)
        #pragma unroll
        for (int j = 0; j < 4; j++)
            #pragma unroll
            for (int q = 0; q < 4; q++) acc[i][j][q] = 0.f;

    int lr = tid >> 2;           // row within A tile (0..63)
    int lq = tid & 3;            // 8-float chunk (0..3)
    bool avalid = (row0 + lr) < M;
    const float* aptr = A + (size_t)(row0 + lr) * KIN + lq * 8;
    int br0 = tid >> 2;          // B row base (0..63)
    int bpart = (tid & 3) * 16;  // 16B part within 64B row

    float fA0[8], fA1[8];
    // ---- prologue: A(0), A(1) regs + B(0) cp.async ----
    if (avalid) {
        const float4* p0 = (const float4*)aptr;
        *(float4*)(fA0)     = p0[0];
        *(float4*)(fA0 + 4) = p0[1];
        const float4* p1 = (const float4*)(aptr + 32);
        *(float4*)(fA1)     = p1[0];
        *(float4*)(fA1 + 4) = p1[1];
    } else {
        #pragma unroll
        for (int i = 0; i < 8; i++) { fA0[i] = 0.f; fA1[i] = 0.f; }
    }
    #pragma unroll
    for (int i = 0; i < 2; i++) {
        int r = br0 + i * 64;
        uint32_t d = sb + OFF_BHI + (uint32_t)r * 80 + bpart;
        CP16(d, (const char*)(g_bhi + (size_t)r * KIN) + bpart);
        CP16(d + (OFF_BLO - OFF_BHI), (const char*)(g_blo + (size_t)r * KIN) + bpart);
    }
    CP_COMMIT();

    #pragma unroll 1
    for (int t = 0; t < NKT; t += 2) {
        GEMM_BODY(t,     0, fA0);
        GEMM_BODY(t + 1, 1, fA1);
    }

    int r = lane >> 2, c = (lane & 3) * 2;
    #pragma unroll
    for (int mi = 0; mi < 2; mi++) {
        int m0 = row0 + wm * 32 + mi * 16 + r;
        #pragma unroll
        for (int ni = 0; ni < 4; ni++) {
            int n = wn * 32 + ni * 8 + c;
            if (m0 < M) {
                __half2 v = __floats2half2_rn(acc[mi][ni][0], acc[mi][ni][1]);
                *(__half2*)&g_hh[(size_t)m0 * NH + n] = v;
            }
            if (m0 + 8 < M) {
                __half2 v = __floats2half2_rn(acc[mi][ni][2], acc[mi][ni][3]);
                *(__half2*)&g_hh[(size_t)(m0 + 8) * NH + n] = v;
            }
        }
    }
}

// ---------------- fused gather + finalize: one warp per dst node (fp16 h) ----------------
__global__ void gather_kernel(const int* __restrict__ perm,
                              const float* __restrict__ b,
                              const float* __restrict__ alpha,
                              float* __restrict__ out, int N) {
    size_t gid = (size_t)blockIdx.x * blockDim.x + threadIdx.x;
    int node = (int)(gid >> 5);
    int lane = (int)(gid & 31);
    if (node >= N) return;

    int start = g_row[node];
    int cnt   = g_deg_in[node];

    float4 acc1 = make_float4(0.f, 0.f, 0.f, 0.f);
    float4 acc2 = make_float4(0.f, 0.f, 0.f, 0.f);

    for (int i = 0; i < cnt; i++) {
        int s  = __ldg(&g_csrc[start + i]);
        int sp = __ldg(&perm[s]);
        float sc = __ldg(&g_norm_out[s]);
        uint2 u1 = *(const uint2*)(g_hh + (size_t)s  * NH + lane * 4);
        uint2 u2 = *(const uint2*)(g_hh + (size_t)sp * NH + lane * 4);
        float2 a = __half22float2(*(__half2*)&u1.x);
        float2 bq = __half22float2(*(__half2*)&u1.y);
        float2 cq = __half22float2(*(__half2*)&u2.x);
        float2 d = __half22float2(*(__half2*)&u2.y);
        acc1.x = fmaf(a.x,  sc, acc1.x);
        acc1.y = fmaf(a.y,  sc, acc1.y);
        acc1.z = fmaf(bq.x, sc, acc1.z);
        acc1.w = fmaf(bq.y, sc, acc1.w);
        acc2.x = fmaf(cq.x, sc, acc2.x);
        acc2.y = fmaf(cq.y, sc, acc2.y);
        acc2.z = fmaf(d.x,  sc, acc2.z);
        acc2.w = fmaf(d.y,  sc, acc2.w);
    }

    float nin = g_norm_in[node];
    float4 bb = *(const float4*)(b      + lane * 4);
    float4 al = *(const float4*)(alpha  + lane * 4);
    float4 ws = *(const float4*)(g_wsum + lane * 4);

    float r1 = 0.f, r2 = 0.f, v;
    v = acc1.x * nin + bb.x; v = (v >= 0.f) ? v : al.x * v; r1 += v * ws.x;
    v = acc1.y * nin + bb.y; v = (v >= 0.f) ? v : al.y * v; r1 += v * ws.y;
    v = acc1.z * nin + bb.z; v = (v >= 0.f) ? v : al.z * v; r1 += v * ws.z;
    v = acc1.w * nin + bb.w; v = (v >= 0.f) ? v : al.w * v; r1 += v * ws.w;
    v = acc2.x * nin + bb.x; v = (v >= 0.f) ? v : al.x * v; r2 += v * ws.x;
    v = acc2.y * nin + bb.y; v = (v >= 0.f) ? v : al.y * v; r2 += v * ws.y;
    v = acc2.z * nin + bb.z; v = (v >= 0.f) ? v : al.z * v; r2 += v * ws.z;
    v = acc2.w * nin + bb.w; v = (v >= 0.f) ? v : al.w * v; r2 += v * ws.w;

    #pragma unroll
    for (int o = 16; o > 0; o >>= 1) {
        r1 += __shfl_xor_sync(0xFFFFFFFFu, r1, o);
        r2 += __shfl_xor_sync(0xFFFFFFFFu, r2, o);
    }
    if (lane == 0) {
        float bs = g_bsum;
        out[node]     = r1 + bs;
        out[N + node] = r2 + bs;
    }
}

// ---------------- launch ----------------
extern "C" void kernel_launch(void* const* d_in, const int* in_sizes, int n_in,
                              void* d_out, int out_size) {
    const float* x     = (const float*)d_in[0];
    const int*   src   = (const int*)  d_in[1];
    const int*   dst   = (const int*)  d_in[2];
    const int*   perm  = (const int*)  d_in[3];
    const float* W     = (const float*)d_in[4];
    const float* b     = (const float*)d_in[5];
    const float* alpha = (const float*)d_in[6];
    const float* mlpW  = (const float*)d_in[7];
    const float* mlpb  = (const float*)d_in[8];
    float* out = (float*)d_out;

    int E = in_sizes[1];
    int N = in_sizes[3];
    if (N > N_MAX || E > E_MAX) return;

    int nb = (N + SCAN_B - 1) / SCAN_B;

    cudaFuncSetAttribute(gemm_mma_kernel,
                         cudaFuncAttributeMaxDynamicSharedMemorySize, GEMM_SMEM);

    zero_kernel   <<<(N + 255) / 256, 256>>>(N);
    degree_kernel <<<(E + 255) / 256, 256>>>(src, dst, E);
    wsplit_kernel <<<(KIN * NH + 255) / 256, 256>>>(W);
    gemm_mma_kernel<<<(N + 63) / 64, 256, GEMM_SMEM>>>(x, N);   // launch index 3 (ncu target)
    scan1_kernel  <<<nb, SCAN_B>>>(N);
    scan2_kernel  <<<1, 512>>>(nb);
    scan3_kernel  <<<nb, SCAN_B>>>(N);
    fill_kernel   <<<(E + 255) / 256, 256>>>(src, dst, E);
    wsum_kernel   <<<NH + 1, 32>>>(mlpW, mlpb);

    size_t gthreads = (size_t)N * 32;
    gather_kernel<<<(unsigned)((gthreads + 255) / 256), 256>>>(perm, b, alpha, out, N);
}

// round 13
// speedup vs baseline: 1.0749x; 1.0333x over previous
#include <cuda_runtime.h>
#include <cuda_bf16.h>
#include <cuda_fp16.h>
#include <cstdint>

#define KIN 512
#define NH  128
#define N_MAX 100000
#define E_MAX 1600000
#define SCAN_B 256
#define NB_MAX ((N_MAX + SCAN_B - 1) / SCAN_B)

// ---------------- scratch (no allocations allowed) ----------------
__device__ __half g_hh[(size_t)N_MAX * NH];    // h = x @ W  (fp16)
__device__ int   g_deg_in [N_MAX];
__device__ int   g_deg_out[N_MAX];
__device__ float g_norm_out[N_MAX];
__device__ float g_norm_in [N_MAX];
__device__ int   g_row  [N_MAX];
__device__ int   g_cur  [N_MAX];
__device__ int   g_csrc [E_MAX];
__device__ int   g_part [NB_MAX];
__device__ int   g_poff [NB_MAX];
__device__ float g_wsum[NH];
__device__ float g_bsum;
__device__ __half g_bhi[NH * KIN];             // W^T fp16 hi : [n][k]
__device__ __half g_blo[NH * KIN];             // W^T fp16 lo : [n][k]

// ================= helpers =================
__device__ __forceinline__ uint32_t smem_u32(const void* p) {
    uint32_t a;
    asm("{ .reg .u64 t; cvta.to.shared.u64 t, %1; cvt.u32.u64 %0, t; }"
        : "=r"(a) : "l"(p));
    return a;
}

__device__ __forceinline__ void ldsm4(uint32_t* r, uint32_t addr) {
    asm volatile("ldmatrix.sync.aligned.m8n8.x4.shared.b16 {%0,%1,%2,%3}, [%4];"
                 : "=r"(r[0]), "=r"(r[1]), "=r"(r[2]), "=r"(r[3]) : "r"(addr));
}

__device__ __forceinline__ void mma_f16(float* d, const uint32_t* a, const uint32_t* b) {
    asm volatile(
        "mma.sync.aligned.m16n8k16.row.col.f32.f16.f16.f32 "
        "{%0,%1,%2,%3}, {%4,%5,%6,%7}, {%8,%9}, {%0,%1,%2,%3};"
        : "+f"(d[0]), "+f"(d[1]), "+f"(d[2]), "+f"(d[3])
        : "r"(a[0]), "r"(a[1]), "r"(a[2]), "r"(a[3]), "r"(b[0]), "r"(b[1]));
}

#define CP16(dst, src) \
    asm volatile("cp.async.cg.shared.global [%0], [%1], 16;" :: "r"(dst), "l"(src))
#define CP_COMMIT() asm volatile("cp.async.commit_group;" ::: "memory")
#define CP_WAIT0()  asm volatile("cp.async.wait_group 0;"  ::: "memory")
#define STS128(a, r0, r1, r2, r3) \
    asm volatile("st.shared.v4.b32 [%0], {%1,%2,%3,%4};" \
                 :: "r"(a), "r"(r0), "r"(r1), "r"(r2), "r"(r3))

// ---------------- zero small scratch ----------------
__global__ void zero_kernel(int N) {
    int i = blockIdx.x * blockDim.x + threadIdx.x;
    if (i < N) { g_deg_in[i] = 0; g_deg_out[i] = 0; }
}

// ---------------- degree counting ----------------
__global__ void degree_kernel(const int* __restrict__ src,
                              const int* __restrict__ dst, int E) {
    int i = blockIdx.x * blockDim.x + threadIdx.x;
    if (i < E) {
        atomicAdd(&g_deg_out[src[i]], 1);
        atomicAdd(&g_deg_in [dst[i]], 1);
    }
}

// ---------------- W transpose + fp16 split: g_bhi/g_blo[n][k] ----------------
__global__ void wsplit_kernel(const float* __restrict__ W) {
    int i = blockIdx.x * blockDim.x + threadIdx.x;
    if (i < KIN * NH) {
        int k = i >> 7, n = i & 127;
        float v = W[i];
        __half h = __float2half_rn(v);
        float l = v - __half2float(h);
        g_bhi[n * KIN + k] = h;
        g_blo[n * KIN + k] = __float2half_rn(l);
    }
}

// ---------------- scans ----------------
__global__ void scan1_kernel(int N) {
    __shared__ int s[SCAN_B];
    int t = threadIdx.x;
    int i = blockIdx.x * SCAN_B + t;
    int v = (i < N) ? g_deg_in[i] : 0;
    s[t] = v;
    __syncthreads();
    int acc = v;
    #pragma unroll
    for (int o = 1; o < SCAN_B; o <<= 1) {
        int add = (t >= o) ? s[t - o] : 0;
        __syncthreads();
        acc += add;
        s[t] = acc;
        __syncthreads();
    }
    if (i < N) g_row[i] = acc - v;
    if (t == SCAN_B - 1) g_part[blockIdx.x] = acc;
}

__global__ void scan2_kernel(int nb) {
    __shared__ int s[512];
    int t = threadIdx.x;
    int v = (t < nb) ? g_part[t] : 0;
    s[t] = v;
    __syncthreads();
    int acc = v;
    #pragma unroll
    for (int o = 1; o < 512; o <<= 1) {
        int add = (t >= o) ? s[t - o] : 0;
        __syncthreads();
        acc += add;
        s[t] = acc;
        __syncthreads();
    }
    if (t < nb) g_poff[t] = acc - v;
}

// scan3 + norm fused
__global__ void scan3_kernel(int N) {
    int i = blockIdx.x * SCAN_B + threadIdx.x;
    if (i < N) {
        int r = g_row[i] + g_poff[blockIdx.x];
        g_row[i] = r;
        g_cur[i] = r;          // fill cursor starts at row offset
        g_norm_out[i] = rsqrtf(fmaxf((float)g_deg_out[i], 1.0f));
        g_norm_in[i]  = rsqrtf(fmaxf((float)g_deg_in[i],  1.0f));
    }
}

// ---------------- CSR fill ----------------
__global__ void fill_kernel(const int* __restrict__ src,
                            const int* __restrict__ dst, int E) {
    int i = blockIdx.x * blockDim.x + threadIdx.x;
    if (i < E) {
        int d = dst[i];
        int pos = atomicAdd(&g_cur[d], 1);
        g_csrc[pos] = src[i];
    }
}

// ---------------- wsum + bsum fused ----------------
__global__ void wsum_kernel(const float* __restrict__ mlpW,
                            const float* __restrict__ mlpb) {
    int j = blockIdx.x;
    int lane = threadIdx.x;
    float s = 0.f;
    if (j < NH) {
        #pragma unroll
        for (int k = lane; k < NH; k += 32) s += mlpW[j * NH + k];
        #pragma unroll
        for (int o = 16; o > 0; o >>= 1) s += __shfl_xor_sync(0xFFFFFFFFu, s, o);
        if (lane == 0) g_wsum[j] = s;
    } else {
        #pragma unroll
        for (int k = lane; k < NH; k += 32) s += mlpb[k];
        #pragma unroll
        for (int o = 16; o > 0; o >>= 1) s += __shfl_xor_sync(0xFFFFFFFFu, s, o);
        if (lane == 0) g_bsum = s;
    }
}

// ============ fp16 HMMA GEMM (A single, W split), 64x128 tile — R10 config ============
// acc = A·Whi + A·Wlo  (A = fp16(x), rounding ~2^-12)
#define PAD 40           // fp16 elems per SMEM row (80B)
#define OFF_BHI 5120     // A: 64 rows x 80B
#define OFF_BLO 15360    // Bhi: 128 rows x 80B
#define STAGE_B 25600
#define GEMM_SMEM (2 * STAGE_B)
#define NKT (KIN / 32)   // 16 K-tiles

__global__ __launch_bounds__(256) void gemm_mma_kernel(const float* __restrict__ A, int M) {
    extern __shared__ char smem[];
    uint32_t sb = smem_u32(smem);

    int tid = threadIdx.x;
    int lane = tid & 31, wid = tid >> 5;
    int wm = wid & 1;       // 2 m-slabs of 32
    int wn = wid >> 1;      // 4 n-slabs of 32
    int row0 = blockIdx.x * 64;

    float acc[2][4][4];
    #pragma unroll
    for (int i = 0; i < 2; i++)
        #pragma unroll
        for (int j = 0; j < 4; j++)
            #pragma unroll
            for (int q = 0; q < 4; q++) acc[i][j][q] = 0.f;

    int lr = tid >> 2;           // row within A tile (0..63)
    int lq = tid & 3;            // 8-float chunk (0..3)
    bool avalid = (row0 + lr) < M;
    const float* aptr = A + (size_t)(row0 + lr) * KIN + lq * 8;
    int br0 = tid >> 2;          // B row base (0..63)
    int bpart = (tid & 3) * 16;  // 16B part within 64B row

    float fA[8];
    if (avalid) {
        const float4* p = (const float4*)aptr;
        *(float4*)(fA)     = p[0];
        *(float4*)(fA + 4) = p[1];
    } else {
        #pragma unroll
        for (int i = 0; i < 8; i++) fA[i] = 0.f;
    }
    #pragma unroll
    for (int i = 0; i < 2; i++) {
        int r = br0 + i * 64;
        uint32_t d = sb + OFF_BHI + (uint32_t)r * 80 + bpart;
        CP16(d, (const char*)(g_bhi + (size_t)r * KIN) + bpart);
        CP16(d + (OFF_BLO - OFF_BHI), (const char*)(g_blo + (size_t)r * KIN) + bpart);
    }
    CP_COMMIT();

    #pragma unroll 1
    for (int t = 0; t < NKT; t++) {
        uint32_t base = sb + (uint32_t)(t & 1) * STAGE_B;

        // ---- convert & store A(t): single fp16, one 16B store ----
        uint32_t hi[4];
        #pragma unroll
        for (int p = 0; p < 4; p++) {
            __half2 h2 = __floats2half2_rn(fA[2 * p], fA[2 * p + 1]);
            hi[p] = *(uint32_t*)&h2;
        }
        uint32_t adst = base + (uint32_t)lr * 80 + (uint32_t)lq * 16;
        STS128(adst, hi[0], hi[1], hi[2], hi[3]);

        CP_WAIT0();
        __syncthreads();

        // ---- prefetch stage t+1 ----
        if (t + 1 < NKT) {
            int k0n = (t + 1) * 32;
            if (avalid) {
                const float4* p = (const float4*)(aptr + k0n);
                *(float4*)(fA)     = p[0];
                *(float4*)(fA + 4) = p[1];
            }
            uint32_t nbase = sb + (uint32_t)((t + 1) & 1) * STAGE_B;
            #pragma unroll
            for (int i = 0; i < 2; i++) {
                int r = br0 + i * 64;
                uint32_t d = nbase + OFF_BHI + (uint32_t)r * 80 + bpart;
                CP16(d, (const char*)(g_bhi + (size_t)r * KIN + k0n) + bpart);
                CP16(d + (OFF_BLO - OFF_BHI),
                     (const char*)(g_blo + (size_t)r * KIN + k0n) + bpart);
            }
            CP_COMMIT();
        }

        // ---- compute stage t: 2 passes (Bhi, Blo) ----
        #pragma unroll
        for (int kk = 0; kk < 2; kk++) {
            int kc = kk * 16 + ((lane >> 4) << 3);
            int arow = wm * 32 + (lane & 15);
            uint32_t ah[2][4];
            #pragma unroll
            for (int mi = 0; mi < 2; mi++) {
                uint32_t addr = base + (uint32_t)((arow + mi * 16) * PAD + kc) * 2;
                ldsm4(ah[mi], addr);
            }
            int brow = wn * 32 + (lane & 15);
            uint32_t bh[4][2], bl[4][2];
            #pragma unroll
            for (int np = 0; np < 2; np++) {
                uint32_t r[4];
                uint32_t addr = base + OFF_BHI + (uint32_t)((brow + np * 16) * PAD + kc) * 2;
                ldsm4(r, addr);
                bh[2 * np][0] = r[0]; bh[2 * np][1] = r[2];
                bh[2 * np + 1][0] = r[1]; bh[2 * np + 1][1] = r[3];
                ldsm4(r, addr + (OFF_BLO - OFF_BHI));
                bl[2 * np][0] = r[0]; bl[2 * np][1] = r[2];
                bl[2 * np + 1][0] = r[1]; bl[2 * np + 1][1] = r[3];
            }
            #pragma unroll
            for (int mi = 0; mi < 2; mi++)
                #pragma unroll
                for (int ni = 0; ni < 4; ni++) {
                    mma_f16(acc[mi][ni], ah[mi], bh[ni]);
                    mma_f16(acc[mi][ni], ah[mi], bl[ni]);
                }
        }
    }

    int r = lane >> 2, c = (lane & 3) * 2;
    #pragma unroll
    for (int mi = 0; mi < 2; mi++) {
        int m0 = row0 + wm * 32 + mi * 16 + r;
        #pragma unroll
        for (int ni = 0; ni < 4; ni++) {
            int n = wn * 32 + ni * 8 + c;
            if (m0 < M) {
                __half2 v = __floats2half2_rn(acc[mi][ni][0], acc[mi][ni][1]);
                *(__half2*)&g_hh[(size_t)m0 * NH + n] = v;
            }
            if (m0 + 8 < M) {
                __half2 v = __floats2half2_rn(acc[mi][ni][2], acc[mi][ni][3]);
                *(__half2*)&g_hh[(size_t)(m0 + 8) * NH + n] = v;
            }
        }
    }
}

// ------- fused gather + finalize: HALF-warp (16 lanes) per dst node, uint4 rows -------
__global__ void gather_kernel(const int* __restrict__ perm,
                              const float* __restrict__ b,
                              const float* __restrict__ alpha,
                              float* __restrict__ out, int N) {
    size_t gid = (size_t)blockIdx.x * blockDim.x + threadIdx.x;
    int node = (int)(gid >> 4);
    int sl   = (int)(gid & 15);          // sub-lane within half-warp
    if (node >= N) return;

    int start = g_row[node];
    int cnt   = g_deg_in[node];
    int foff  = sl * 8;                  // 8 features per lane

    float acc1[8], acc2[8];
    #pragma unroll
    for (int q = 0; q < 8; q++) { acc1[q] = 0.f; acc2[q] = 0.f; }

    for (int i = 0; i < cnt; i++) {
        int s  = __ldg(&g_csrc[start + i]);
        int sp = __ldg(&perm[s]);
        float sc = __ldg(&g_norm_out[s]);
        uint4 u1 = *(const uint4*)(g_hh + (size_t)s  * NH + foff);
        uint4 u2 = *(const uint4*)(g_hh + (size_t)sp * NH + foff);
        float2 p;
        p = __half22float2(*(__half2*)&u1.x); acc1[0] = fmaf(p.x, sc, acc1[0]); acc1[1] = fmaf(p.y, sc, acc1[1]);
        p = __half22float2(*(__half2*)&u1.y); acc1[2] = fmaf(p.x, sc, acc1[2]); acc1[3] = fmaf(p.y, sc, acc1[3]);
        p = __half22float2(*(__half2*)&u1.z); acc1[4] = fmaf(p.x, sc, acc1[4]); acc1[5] = fmaf(p.y, sc, acc1[5]);
        p = __half22float2(*(__half2*)&u1.w); acc1[6] = fmaf(p.x, sc, acc1[6]); acc1[7] = fmaf(p.y, sc, acc1[7]);
        p = __half22float2(*(__half2*)&u2.x); acc2[0] = fmaf(p.x, sc, acc2[0]); acc2[1] = fmaf(p.y, sc, acc2[1]);
        p = __half22float2(*(__half2*)&u2.y); acc2[2] = fmaf(p.x, sc, acc2[2]); acc2[3] = fmaf(p.y, sc, acc2[3]);
        p = __half22float2(*(__half2*)&u2.z); acc2[4] = fmaf(p.x, sc, acc2[4]); acc2[5] = fmaf(p.y, sc, acc2[5]);
        p = __half22float2(*(__half2*)&u2.w); acc2[6] = fmaf(p.x, sc, acc2[6]); acc2[7] = fmaf(p.y, sc, acc2[7]);
    }

    float nin = g_norm_in[node];
    float bb[8], al[8], ws[8];
    *(float4*)(bb)     = *(const float4*)(b      + foff);
    *(float4*)(bb + 4) = *(const float4*)(b      + foff + 4);
    *(float4*)(al)     = *(const float4*)(alpha  + foff);
    *(float4*)(al + 4) = *(const float4*)(alpha  + foff + 4);
    *(float4*)(ws)     = *(const float4*)(g_wsum + foff);
    *(float4*)(ws + 4) = *(const float4*)(g_wsum + foff + 4);

    float r1 = 0.f, r2 = 0.f;
    #pragma unroll
    for (int q = 0; q < 8; q++) {
        float v1 = acc1[q] * nin + bb[q];
        v1 = (v1 >= 0.f) ? v1 : al[q] * v1;
        r1 = fmaf(v1, ws[q], r1);
        float v2 = acc2[q] * nin + bb[q];
        v2 = (v2 >= 0.f) ? v2 : al[q] * v2;
        r2 = fmaf(v2, ws[q], r2);
    }

    // reduce within 16-lane half-warp (xor offsets stay inside the half)
    #pragma unroll
    for (int o = 8; o > 0; o >>= 1) {
        r1 += __shfl_xor_sync(0xFFFFFFFFu, r1, o);
        r2 += __shfl_xor_sync(0xFFFFFFFFu, r2, o);
    }
    if (sl == 0) {
        float bs = g_bsum;
        out[node]     = r1 + bs;
        out[N + node] = r2 + bs;
    }
}

// ---------------- launch ----------------
extern "C" void kernel_launch(void* const* d_in, const int* in_sizes, int n_in,
                              void* d_out, int out_size) {
    const float* x     = (const float*)d_in[0];
    const int*   src   = (const int*)  d_in[1];
    const int*   dst   = (const int*)  d_in[2];
    const int*   perm  = (const int*)  d_in[3];
    const float* W     = (const float*)d_in[4];
    const float* b     = (const float*)d_in[5];
    const float* alpha = (const float*)d_in[6];
    const float* mlpW  = (const float*)d_in[7];
    const float* mlpb  = (const float*)d_in[8];
    float* out = (float*)d_out;

    int E = in_sizes[1];
    int N = in_sizes[3];
    if (N > N_MAX || E > E_MAX) return;

    int nb = (N + SCAN_B - 1) / SCAN_B;

    cudaFuncSetAttribute(gemm_mma_kernel,
                         cudaFuncAttributeMaxDynamicSharedMemorySize, GEMM_SMEM);

    zero_kernel   <<<(N + 255) / 256, 256>>>(N);
    degree_kernel <<<(E + 255) / 256, 256>>>(src, dst, E);
    wsplit_kernel <<<(KIN * NH + 255) / 256, 256>>>(W);
    gemm_mma_kernel<<<(N + 63) / 64, 256, GEMM_SMEM>>>(x, N);   // launch index 3 (ncu target)
    scan1_kernel  <<<nb, SCAN_B>>>(N);
    scan2_kernel  <<<1, 512>>>(nb);
    scan3_kernel  <<<nb, SCAN_B>>>(N);
    fill_kernel   <<<(E + 255) / 256, 256>>>(src, dst, E);
    wsum_kernel   <<<NH + 1, 32>>>(mlpW, mlpb);

    size_t gthreads = (size_t)N * 16;
    gather_kernel<<<(unsigned)((gthreads + 255) / 256), 256>>>(perm, b, alpha, out, N);
}

// round 14
// speedup vs baseline: 1.0913x; 1.0152x over previous
#include <cuda_runtime.h>
#include <cuda_bf16.h>
#include <cuda_fp16.h>
#include <cstdint>

#define KIN 512
#define NH  128
#define N_MAX 100000
#define E_MAX 1600000
#define SCAN_B 256
#define NB_MAX ((N_MAX + SCAN_B - 1) / SCAN_B)

// ---------------- scratch (no allocations allowed) ----------------
__device__ __half g_hh[(size_t)N_MAX * NH];    // h = x @ W  (fp16)
__device__ int   g_deg_in [N_MAX];
__device__ int   g_deg_out[N_MAX];
__device__ float g_norm_out[N_MAX];
__device__ float g_norm_in [N_MAX];
__device__ int   g_row  [N_MAX];
__device__ int   g_cur  [N_MAX];
__device__ int   g_csrc [E_MAX];
__device__ unsigned long long g_state[NB_MAX]; // lookback: (flag<<32)|value
__device__ float g_wsum[NH];
__device__ float g_bsum;
__device__ __half g_bhi[NH * KIN];             // W^T fp16 hi : [n][k]
__device__ __half g_blo[NH * KIN];             // W^T fp16 lo : [n][k]

// ================= helpers =================
__device__ __forceinline__ uint32_t smem_u32(const void* p) {
    uint32_t a;
    asm("{ .reg .u64 t; cvta.to.shared.u64 t, %1; cvt.u32.u64 %0, t; }"
        : "=r"(a) : "l"(p));
    return a;
}

__device__ __forceinline__ void ldsm4(uint32_t* r, uint32_t addr) {
    asm volatile("ldmatrix.sync.aligned.m8n8.x4.shared.b16 {%0,%1,%2,%3}, [%4];"
                 : "=r"(r[0]), "=r"(r[1]), "=r"(r[2]), "=r"(r[3]) : "r"(addr));
}

__device__ __forceinline__ void mma_f16(float* d, const uint32_t* a, const uint32_t* b) {
    asm volatile(
        "mma.sync.aligned.m16n8k16.row.col.f32.f16.f16.f32 "
        "{%0,%1,%2,%3}, {%4,%5,%6,%7}, {%8,%9}, {%0,%1,%2,%3};"
        : "+f"(d[0]), "+f"(d[1]), "+f"(d[2]), "+f"(d[3])
        : "r"(a[0]), "r"(a[1]), "r"(a[2]), "r"(a[3]), "r"(b[0]), "r"(b[1]));
}

#define CP16(dst, src) \
    asm volatile("cp.async.cg.shared.global [%0], [%1], 16;" :: "r"(dst), "l"(src))
#define CP_COMMIT() asm volatile("cp.async.commit_group;" ::: "memory")
#define CP_WAIT0()  asm volatile("cp.async.wait_group 0;"  ::: "memory")
#define STS128(a, r0, r1, r2, r3) \
    asm volatile("st.shared.v4.b32 [%0], {%1,%2,%3,%4};" \
                 :: "r"(a), "r"(r0), "r"(r1), "r"(r2), "r"(r3))

// ---------------- prep: zero deg/state + W split + wsum + bsum (fused) ----------------
__global__ void prep_kernel(int N, int nb,
                            const float* __restrict__ W,
                            const float* __restrict__ mlpW,
                            const float* __restrict__ mlpb) {
    int i = blockIdx.x * blockDim.x + threadIdx.x;
    if (i < N) { g_deg_in[i] = 0; g_deg_out[i] = 0; }
    if (i < nb) g_state[i] = 0ULL;
    if (i < KIN * NH) {
        int k = i >> 7, n = i & 127;
        float v = W[i];
        __half h = __float2half_rn(v);
        g_bhi[n * KIN + k] = h;
        g_blo[n * KIN + k] = __float2half_rn(v - __half2float(h));
    }
    if (blockIdx.x < NH && threadIdx.x < 32) {
        int lane = threadIdx.x;
        float s = 0.f;
        #pragma unroll
        for (int k = lane; k < NH; k += 32) s += mlpW[blockIdx.x * NH + k];
        #pragma unroll
        for (int o = 16; o > 0; o >>= 1) s += __shfl_xor_sync(0xFFFFFFFFu, s, o);
        if (lane == 0) g_wsum[blockIdx.x] = s;
    }
    if (blockIdx.x == NH && threadIdx.x < 32) {
        int lane = threadIdx.x;
        float s = 0.f;
        #pragma unroll
        for (int k = lane; k < NH; k += 32) s += mlpb[k];
        #pragma unroll
        for (int o = 16; o > 0; o >>= 1) s += __shfl_xor_sync(0xFFFFFFFFu, s, o);
        if (lane == 0) g_bsum = s;
    }
}

// ---------------- degree counting ----------------
__global__ void degree_kernel(const int* __restrict__ src,
                              const int* __restrict__ dst, int E) {
    int i = blockIdx.x * blockDim.x + threadIdx.x;
    if (i < E) {
        atomicAdd(&g_deg_out[src[i]], 1);
        atomicAdd(&g_deg_in [dst[i]], 1);
    }
}

// ------- single-pass scan (decoupled lookback) + norm + cursor init (fused) -------
__global__ void scan_kernel(int N) {
    __shared__ int s[SCAN_B];
    __shared__ int s_base;
    int t = threadIdx.x;
    int b = blockIdx.x;
    int i = b * SCAN_B + t;
    int v = (i < N) ? g_deg_in[i] : 0;
    s[t] = v;
    __syncthreads();
    int acc = v;
    #pragma unroll
    for (int o = 1; o < SCAN_B; o <<= 1) {
        int add = (t >= o) ? s[t - o] : 0;
        __syncthreads();
        acc += add;
        s[t] = acc;
        __syncthreads();
    }
    int tot = s[SCAN_B - 1];

    // publish block aggregate (block 0 publishes inclusive immediately)
    if (t == 0) {
        unsigned long long st =
            ((unsigned long long)(b == 0 ? 2u : 1u) << 32) | (unsigned)tot;
        atomicExch(&g_state[b], st);
        if (b == 0) s_base = 0;
    }

    // warp-parallel lookback (warp 0)
    if (b > 0 && t < 32) {
        int base = 0;
        int idx = b - 1;
        for (;;) {
            int j = idx - t;
            int f, val;
            if (j >= 0) {
                unsigned long long st;
                do { st = atomicAdd(&g_state[j], 0ULL); } while ((st >> 32) == 0);
                f = (int)(st >> 32);
                val = (int)(st & 0xffffffffULL);
            } else { f = 2; val = 0; }
            unsigned incmask = __ballot_sync(0xffffffffu, f == 2);
            int firstinc = __ffs(incmask) - 1;   // closest inclusive lane (or -1)
            int contrib;
            if (incmask)
                contrib = (t <= firstinc) ? val : 0;   // aggs before + inclusive at firstinc
            else
                contrib = val;                          // all aggregates, continue back
            #pragma unroll
            for (int o = 16; o > 0; o >>= 1)
                contrib += __shfl_xor_sync(0xffffffffu, contrib, o);
            base += contrib;
            if (incmask) break;
            idx -= 32;
        }
        if (t == 0) {
            s_base = base;
            unsigned long long st = (2ULL << 32) | (unsigned)(base + tot);
            atomicExch(&g_state[b], st);
        }
    }
    __syncthreads();

    if (i < N) {
        int r = s_base + acc - v;
        g_row[i] = r;
        g_cur[i] = r;
        g_norm_out[i] = rsqrtf(fmaxf((float)g_deg_out[i], 1.0f));
        g_norm_in[i]  = rsqrtf(fmaxf((float)g_deg_in[i],  1.0f));
    }
}

// ---------------- CSR fill ----------------
__global__ void fill_kernel(const int* __restrict__ src,
                            const int* __restrict__ dst, int E) {
    int i = blockIdx.x * blockDim.x + threadIdx.x;
    if (i < E) {
        int d = dst[i];
        int pos = atomicAdd(&g_cur[d], 1);
        g_csrc[pos] = src[i];
    }
}

// ============ fp16 HMMA GEMM (A single, W split), 64x128 tile — R10 config (protected) ============
#define PAD 40           // fp16 elems per SMEM row (80B)
#define OFF_BHI 5120     // A: 64 rows x 80B
#define OFF_BLO 15360    // Bhi: 128 rows x 80B
#define STAGE_B 25600
#define GEMM_SMEM (2 * STAGE_B)
#define NKT (KIN / 32)   // 16 K-tiles

__global__ __launch_bounds__(256) void gemm_mma_kernel(const float* __restrict__ A, int M) {
    extern __shared__ char smem[];
    uint32_t sb = smem_u32(smem);

    int tid = threadIdx.x;
    int lane = tid & 31, wid = tid >> 5;
    int wm = wid & 1;       // 2 m-slabs of 32
    int wn = wid >> 1;      // 4 n-slabs of 32
    int row0 = blockIdx.x * 64;

    float acc[2][4][4];
    #pragma unroll
    for (int i = 0; i < 2; i++)
        #pragma unroll
        for (int j = 0; j < 4; j++)
            #pragma unroll
            for (int q = 0; q < 4; q++) acc[i][j][q] = 0.f;

    int lr = tid >> 2;           // row within A tile (0..63)
    int lq = tid & 3;            // 8-float chunk (0..3)
    bool avalid = (row0 + lr) < M;
    const float* aptr = A + (size_t)(row0 + lr) * KIN + lq * 8;
    int br0 = tid >> 2;          // B row base (0..63)
    int bpart = (tid & 3) * 16;  // 16B part within 64B row

    float fA[8];
    if (avalid) {
        const float4* p = (const float4*)aptr;
        *(float4*)(fA)     = p[0];
        *(float4*)(fA + 4) = p[1];
    } else {
        #pragma unroll
        for (int i = 0; i < 8; i++) fA[i] = 0.f;
    }
    #pragma unroll
    for (int i = 0; i < 2; i++) {
        int r = br0 + i * 64;
        uint32_t d = sb + OFF_BHI + (uint32_t)r * 80 + bpart;
        CP16(d, (const char*)(g_bhi + (size_t)r * KIN) + bpart);
        CP16(d + (OFF_BLO - OFF_BHI), (const char*)(g_blo + (size_t)r * KIN) + bpart);
    }
    CP_COMMIT();

    #pragma unroll 1
    for (int t = 0; t < NKT; t++) {
        uint32_t base = sb + (uint32_t)(t & 1) * STAGE_B;

        uint32_t hi[4];
        #pragma unroll
        for (int p = 0; p < 4; p++) {
            __half2 h2 = __floats2half2_rn(fA[2 * p], fA[2 * p + 1]);
            hi[p] = *(uint32_t*)&h2;
        }
        uint32_t adst = base + (uint32_t)lr * 80 + (uint32_t)lq * 16;
        STS128(adst, hi[0], hi[1], hi[2], hi[3]);

        CP_WAIT0();
        __syncthreads();

        if (t + 1 < NKT) {
            int k0n = (t + 1) * 32;
            if (avalid) {
                const float4* p = (const float4*)(aptr + k0n);
                *(float4*)(fA)     = p[0];
                *(float4*)(fA + 4) = p[1];
            }
            uint32_t nbase = sb + (uint32_t)((t + 1) & 1) * STAGE_B;
            #pragma unroll
            for (int i = 0; i < 2; i++) {
                int r = br0 + i * 64;
                uint32_t d = nbase + OFF_BHI + (uint32_t)r * 80 + bpart;
                CP16(d, (const char*)(g_bhi + (size_t)r * KIN + k0n) + bpart);
                CP16(d + (OFF_BLO - OFF_BHI),
                     (const char*)(g_blo + (size_t)r * KIN + k0n) + bpart);
            }
            CP_COMMIT();
        }

        #pragma unroll
        for (int kk = 0; kk < 2; kk++) {
            int kc = kk * 16 + ((lane >> 4) << 3);
            int arow = wm * 32 + (lane & 15);
            uint32_t ah[2][4];
            #pragma unroll
            for (int mi = 0; mi < 2; mi++) {
                uint32_t addr = base + (uint32_t)((arow + mi * 16) * PAD + kc) * 2;
                ldsm4(ah[mi], addr);
            }
            int brow = wn * 32 + (lane & 15);
            uint32_t bh[4][2], bl[4][2];
            #pragma unroll
            for (int np = 0; np < 2; np++) {
                uint32_t r[4];
                uint32_t addr = base + OFF_BHI + (uint32_t)((brow + np * 16) * PAD + kc) * 2;
                ldsm4(r, addr);
                bh[2 * np][0] = r[0]; bh[2 * np][1] = r[2];
                bh[2 * np + 1][0] = r[1]; bh[2 * np + 1][1] = r[3];
                ldsm4(r, addr + (OFF_BLO - OFF_BHI));
                bl[2 * np][0] = r[0]; bl[2 * np][1] = r[2];
                bl[2 * np + 1][0] = r[1]; bl[2 * np + 1][1] = r[3];
            }
            #pragma unroll
            for (int mi = 0; mi < 2; mi++)
                #pragma unroll
                for (int ni = 0; ni < 4; ni++) {
                    mma_f16(acc[mi][ni], ah[mi], bh[ni]);
                    mma_f16(acc[mi][ni], ah[mi], bl[ni]);
                }
        }
    }

    int r = lane >> 2, c = (lane & 3) * 2;
    #pragma unroll
    for (int mi = 0; mi < 2; mi++) {
        int m0 = row0 + wm * 32 + mi * 16 + r;
        #pragma unroll
        for (int ni = 0; ni < 4; ni++) {
            int n = wn * 32 + ni * 8 + c;
            if (m0 < M) {
                __half2 v = __floats2half2_rn(acc[mi][ni][0], acc[mi][ni][1]);
                *(__half2*)&g_hh[(size_t)m0 * NH + n] = v;
            }
            if (m0 + 8 < M) {
                __half2 v = __floats2half2_rn(acc[mi][ni][2], acc[mi][ni][3]);
                *(__half2*)&g_hh[(size_t)(m0 + 8) * NH + n] = v;
            }
        }
    }
}

// ------- fused gather + finalize: half-warp per dst node (R13 config, protected) -------
__global__ void gather_kernel(const int* __restrict__ perm,
                              const float* __restrict__ b,
                              const float* __restrict__ alpha,
                              float* __restrict__ out, int N) {
    size_t gid = (size_t)blockIdx.x * blockDim.x + threadIdx.x;
    int node = (int)(gid >> 4);
    int sl   = (int)(gid & 15);
    if (node >= N) return;

    int start = g_row[node];
    int cnt   = g_deg_in[node];
    int foff  = sl * 8;

    float acc1[8], acc2[8];
    #pragma unroll
    for (int q = 0; q < 8; q++) { acc1[q] = 0.f; acc2[q] = 0.f; }

    for (int i = 0; i < cnt; i++) {
        int s  = __ldg(&g_csrc[start + i]);
        int sp = __ldg(&perm[s]);
        float sc = __ldg(&g_norm_out[s]);
        uint4 u1 = *(const uint4*)(g_hh + (size_t)s  * NH + foff);
        uint4 u2 = *(const uint4*)(g_hh + (size_t)sp * NH + foff);
        float2 p;
        p = __half22float2(*(__half2*)&u1.x); acc1[0] = fmaf(p.x, sc, acc1[0]); acc1[1] = fmaf(p.y, sc, acc1[1]);
        p = __half22float2(*(__half2*)&u1.y); acc1[2] = fmaf(p.x, sc, acc1[2]); acc1[3] = fmaf(p.y, sc, acc1[3]);
        p = __half22float2(*(__half2*)&u1.z); acc1[4] = fmaf(p.x, sc, acc1[4]); acc1[5] = fmaf(p.y, sc, acc1[5]);
        p = __half22float2(*(__half2*)&u1.w); acc1[6] = fmaf(p.x, sc, acc1[6]); acc1[7] = fmaf(p.y, sc, acc1[7]);
        p = __half22float2(*(__half2*)&u2.x); acc2[0] = fmaf(p.x, sc, acc2[0]); acc2[1] = fmaf(p.y, sc, acc2[1]);
        p = __half22float2(*(__half2*)&u2.y); acc2[2] = fmaf(p.x, sc, acc2[2]); acc2[3] = fmaf(p.y, sc, acc2[3]);
        p = __half22float2(*(__half2*)&u2.z); acc2[4] = fmaf(p.x, sc, acc2[4]); acc2[5] = fmaf(p.y, sc, acc2[5]);
        p = __half22float2(*(__half2*)&u2.w); acc2[6] = fmaf(p.x, sc, acc2[6]); acc2[7] = fmaf(p.y, sc, acc2[7]);
    }

    float nin = g_norm_in[node];
    float bb[8], al[8], ws[8];
    *(float4*)(bb)     = *(const float4*)(b      + foff);
    *(float4*)(bb + 4) = *(const float4*)(b      + foff + 4);
    *(float4*)(al)     = *(const float4*)(alpha  + foff);
    *(float4*)(al + 4) = *(const float4*)(alpha  + foff + 4);
    *(float4*)(ws)     = *(const float4*)(g_wsum + foff);
    *(float4*)(ws + 4) = *(const float4*)(g_wsum + foff + 4);

    float r1 = 0.f, r2 = 0.f;
    #pragma unroll
    for (int q = 0; q < 8; q++) {
        float v1 = acc1[q] * nin + bb[q];
        v1 = (v1 >= 0.f) ? v1 : al[q] * v1;
        r1 = fmaf(v1, ws[q], r1);
        float v2 = acc2[q] * nin + bb[q];
        v2 = (v2 >= 0.f) ? v2 : al[q] * v2;
        r2 = fmaf(v2, ws[q], r2);
    }

    #pragma unroll
    for (int o = 8; o > 0; o >>= 1) {
        r1 += __shfl_xor_sync(0xFFFFFFFFu, r1, o);
        r2 += __shfl_xor_sync(0xFFFFFFFFu, r2, o);
    }
    if (sl == 0) {
        float bs = g_bsum;
        out[node]     = r1 + bs;
        out[N + node] = r2 + bs;
    }
}

// ---------------- launch: 6 kernels ----------------
extern "C" void kernel_launch(void* const* d_in, const int* in_sizes, int n_in,
                              void* d_out, int out_size) {
    const float* x     = (const float*)d_in[0];
    const int*   src   = (const int*)  d_in[1];
    const int*   dst   = (const int*)  d_in[2];
    const int*   perm  = (const int*)  d_in[3];
    const float* W     = (const float*)d_in[4];
    const float* b     = (const float*)d_in[5];
    const float* alpha = (const float*)d_in[6];
    const float* mlpW  = (const float*)d_in[7];
    const float* mlpb  = (const float*)d_in[8];
    float* out = (float*)d_out;

    int E = in_sizes[1];
    int N = in_sizes[3];
    if (N > N_MAX || E > E_MAX) return;

    int nb = (N + SCAN_B - 1) / SCAN_B;

    cudaFuncSetAttribute(gemm_mma_kernel,
                         cudaFuncAttributeMaxDynamicSharedMemorySize, GEMM_SMEM);

    prep_kernel   <<<nb, SCAN_B>>>(N, nb, W, mlpW, mlpb);
    degree_kernel <<<(E + 255) / 256, 256>>>(src, dst, E);
    gemm_mma_kernel<<<(N + 63) / 64, 256, GEMM_SMEM>>>(x, N);
    scan_kernel   <<<nb, SCAN_B>>>(N);
    fill_kernel   <<<(E + 255) / 256, 256>>>(src, dst, E);

    size_t gthreads = (size_t)N * 16;
    gather_kernel<<<(unsigned)((gthreads + 255) / 256), 256>>>(perm, b, alpha, out, N);
}

// round 15
// speedup vs baseline: 1.1017x; 1.0095x over previous
#include <cuda_runtime.h>
#include <cuda_bf16.h>
#include <cuda_fp16.h>
#include <cstdint>

#define KIN 512
#define NH  128
#define N_MAX 100000
#define E_MAX 1600000
#define SCAN_B 256
#define NB_MAX ((N_MAX + SCAN_B - 1) / SCAN_B)

// ---------------- scratch (no allocations allowed; all start zeroed) ----------------
__device__ __half g_hh[(size_t)N_MAX * NH];    // h = x @ W  (fp16)
__device__ int   g_deg_in [N_MAX];             // zeroed by gather tail each iteration
__device__ int   g_deg_out[N_MAX];             // zeroed by gather tail each iteration
__device__ float g_norm_out[N_MAX];
__device__ float g_norm_in [N_MAX];
__device__ int   g_row  [N_MAX];
__device__ int   g_cur  [N_MAX];
__device__ int   g_csrc [E_MAX];
__device__ unsigned long long g_state[NB_MAX]; // zeroed by fill tail each iteration
__device__ float g_wsum[NH];
__device__ float g_bsum;
__device__ __half g_bhi[NH * KIN];             // W^T fp16 hi : [n][k]
__device__ __half g_blo[NH * KIN];             // W^T fp16 lo : [n][k]

// ================= helpers =================
__device__ __forceinline__ uint32_t smem_u32(const void* p) {
    uint32_t a;
    asm("{ .reg .u64 t; cvta.to.shared.u64 t, %1; cvt.u32.u64 %0, t; }"
        : "=r"(a) : "l"(p));
    return a;
}

__device__ __forceinline__ void ldsm4(uint32_t* r, uint32_t addr) {
    asm volatile("ldmatrix.sync.aligned.m8n8.x4.shared.b16 {%0,%1,%2,%3}, [%4];"
                 : "=r"(r[0]), "=r"(r[1]), "=r"(r[2]), "=r"(r[3]) : "r"(addr));
}

__device__ __forceinline__ void mma_f16(float* d, const uint32_t* a, const uint32_t* b) {
    asm volatile(
        "mma.sync.aligned.m16n8k16.row.col.f32.f16.f16.f32 "
        "{%0,%1,%2,%3}, {%4,%5,%6,%7}, {%8,%9}, {%0,%1,%2,%3};"
        : "+f"(d[0]), "+f"(d[1]), "+f"(d[2]), "+f"(d[3])
        : "r"(a[0]), "r"(a[1]), "r"(a[2]), "r"(a[3]), "r"(b[0]), "r"(b[1]));
}

#define CP16(dst, src) \
    asm volatile("cp.async.cg.shared.global [%0], [%1], 16;" :: "r"(dst), "l"(src))
#define CP_COMMIT() asm volatile("cp.async.commit_group;" ::: "memory")
#define CP_WAIT0()  asm volatile("cp.async.wait_group 0;"  ::: "memory")
#define STS128(a, r0, r1, r2, r3) \
    asm volatile("st.shared.v4.b32 [%0], {%1,%2,%3,%4};" \
                 :: "r"(a), "r"(r0), "r"(r1), "r"(r2), "r"(r3))

// ------- fused: degree atomics + W split + wsum + bsum (deg arrays pre-zeroed) -------
__global__ void degprep_kernel(const int* __restrict__ src,
                               const int* __restrict__ dst, int E,
                               const float* __restrict__ W,
                               const float* __restrict__ mlpW,
                               const float* __restrict__ mlpb) {
    int i = blockIdx.x * blockDim.x + threadIdx.x;
    if (i < KIN * NH) {
        int k = i >> 7, n = i & 127;
        float v = W[i];
        __half h = __float2half_rn(v);
        g_bhi[n * KIN + k] = h;
        g_blo[n * KIN + k] = __float2half_rn(v - __half2float(h));
    }
    if (blockIdx.x < NH && threadIdx.x < 32) {
        int lane = threadIdx.x;
        float s = 0.f;
        #pragma unroll
        for (int k = lane; k < NH; k += 32) s += mlpW[blockIdx.x * NH + k];
        #pragma unroll
        for (int o = 16; o > 0; o >>= 1) s += __shfl_xor_sync(0xFFFFFFFFu, s, o);
        if (lane == 0) g_wsum[blockIdx.x] = s;
    }
    if (blockIdx.x == NH && threadIdx.x < 32) {
        int lane = threadIdx.x;
        float s = 0.f;
        #pragma unroll
        for (int k = lane; k < NH; k += 32) s += mlpb[k];
        #pragma unroll
        for (int o = 16; o > 0; o >>= 1) s += __shfl_xor_sync(0xFFFFFFFFu, s, o);
        if (lane == 0) g_bsum = s;
    }
    if (i < E) {
        atomicAdd(&g_deg_out[src[i]], 1);
        atomicAdd(&g_deg_in [dst[i]], 1);
    }
}

// ------- single-pass scan (warp-shuffle + decoupled lookback) + norm + cursor -------
__global__ void scan_kernel(int N) {
    __shared__ int swsum[8];
    __shared__ int s_base;
    int t = threadIdx.x;
    int b = blockIdx.x;
    int i = b * SCAN_B + t;
    int lane = t & 31, widx = t >> 5;
    int v = (i < N) ? g_deg_in[i] : 0;

    // warp inclusive scan
    int acc = v;
    #pragma unroll
    for (int o = 1; o < 32; o <<= 1) {
        int n = __shfl_up_sync(0xFFFFFFFFu, acc, o);
        if (lane >= o) acc += n;
    }
    if (lane == 31) swsum[widx] = acc;
    __syncthreads();

    // warp 0 scans the 8 warp totals (inclusive)
    if (widx == 0) {
        int wv = (lane < 8) ? swsum[lane] : 0;
        #pragma unroll
        for (int o = 1; o < 8; o <<= 1) {
            int n = __shfl_up_sync(0xFFFFFFFFu, wv, o);
            if (lane >= o) wv += n;
        }
        if (lane < 8) swsum[lane] = wv;
    }
    __syncthreads();

    int woff = (widx > 0) ? swsum[widx - 1] : 0;
    acc += woff;                       // block-inclusive
    int tot = swsum[7];

    // publish block aggregate (block 0 publishes inclusive immediately)
    if (t == 0) {
        unsigned long long st =
            ((unsigned long long)(b == 0 ? 2u : 1u) << 32) | (unsigned)tot;
        atomicExch(&g_state[b], st);
        if (b == 0) s_base = 0;
    }

    // warp-parallel lookback (warp 0)
    if (b > 0 && t < 32) {
        int base = 0;
        int idx = b - 1;
        for (;;) {
            int j = idx - t;
            int f, val;
            if (j >= 0) {
                unsigned long long st;
                do { st = atomicAdd(&g_state[j], 0ULL); } while ((st >> 32) == 0);
                f = (int)(st >> 32);
                val = (int)(st & 0xffffffffULL);
            } else { f = 2; val = 0; }
            unsigned incmask = __ballot_sync(0xffffffffu, f == 2);
            int firstinc = __ffs(incmask) - 1;
            int contrib;
            if (incmask)
                contrib = (t <= firstinc) ? val : 0;
            else
                contrib = val;
            #pragma unroll
            for (int o = 16; o > 0; o >>= 1)
                contrib += __shfl_xor_sync(0xffffffffu, contrib, o);
            base += contrib;
            if (incmask) break;
            idx -= 32;
        }
        if (t == 0) {
            s_base = base;
            unsigned long long st = (2ULL << 32) | (unsigned)(base + tot);
            atomicExch(&g_state[b], st);
        }
    }
    __syncthreads();

    if (i < N) {
        int r = s_base + acc - v;      // exclusive
        g_row[i] = r;
        g_cur[i] = r;
        g_norm_out[i] = rsqrtf(fmaxf((float)g_deg_out[i], 1.0f));
        g_norm_in[i]  = rsqrtf(fmaxf((float)g_deg_in[i],  1.0f));
    }
}

// ---------------- CSR fill (+ reset lookback state for next iteration) ----------------
__global__ void fill_kernel(const int* __restrict__ src,
                            const int* __restrict__ dst, int E, int nb) {
    int i = blockIdx.x * blockDim.x + threadIdx.x;
    if (i < nb) g_state[i] = 0ULL;     // scan fully done; safe to reset
    if (i < E) {
        int d = dst[i];
        int pos = atomicAdd(&g_cur[d], 1);
        g_csrc[pos] = src[i];
    }
}

// ============ fp16 HMMA GEMM (A single, W split), 64x128 tile — R10 config (protected) ============
#define PAD 40           // fp16 elems per SMEM row (80B)
#define OFF_BHI 5120     // A: 64 rows x 80B
#define OFF_BLO 15360    // Bhi: 128 rows x 80B
#define STAGE_B 25600
#define GEMM_SMEM (2 * STAGE_B)
#define NKT (KIN / 32)   // 16 K-tiles

__global__ __launch_bounds__(256) void gemm_mma_kernel(const float* __restrict__ A, int M) {
    extern __shared__ char smem[];
    uint32_t sb = smem_u32(smem);

    int tid = threadIdx.x;
    int lane = tid & 31, wid = tid >> 5;
    int wm = wid & 1;       // 2 m-slabs of 32
    int wn = wid >> 1;      // 4 n-slabs of 32
    int row0 = blockIdx.x * 64;

    float acc[2][4][4];
    #pragma unroll
    for (int i = 0; i < 2; i++)
        #pragma unroll
        for (int j = 0; j < 4; j++)
            #pragma unroll
            for (int q = 0; q < 4; q++) acc[i][j][q] = 0.f;

    int lr = tid >> 2;           // row within A tile (0..63)
    int lq = tid & 3;            // 8-float chunk (0..3)
    bool avalid = (row0 + lr) < M;
    const float* aptr = A + (size_t)(row0 + lr) * KIN + lq * 8;
    int br0 = tid >> 2;          // B row base (0..63)
    int bpart = (tid & 3) * 16;  // 16B part within 64B row

    float fA[8];
    if (avalid) {
        const float4* p = (const float4*)aptr;
        *(float4*)(fA)     = p[0];
        *(float4*)(fA + 4) = p[1];
    } else {
        #pragma unroll
        for (int i = 0; i < 8; i++) fA[i] = 0.f;
    }
    #pragma unroll
    for (int i = 0; i < 2; i++) {
        int r = br0 + i * 64;
        uint32_t d = sb + OFF_BHI + (uint32_t)r * 80 + bpart;
        CP16(d, (const char*)(g_bhi + (size_t)r * KIN) + bpart);
        CP16(d + (OFF_BLO - OFF_BHI), (const char*)(g_blo + (size_t)r * KIN) + bpart);
    }
    CP_COMMIT();

    #pragma unroll 1
    for (int t = 0; t < NKT; t++) {
        uint32_t base = sb + (uint32_t)(t & 1) * STAGE_B;

        uint32_t hi[4];
        #pragma unroll
        for (int p = 0; p < 4; p++) {
            __half2 h2 = __floats2half2_rn(fA[2 * p], fA[2 * p + 1]);
            hi[p] = *(uint32_t*)&h2;
        }
        uint32_t adst = base + (uint32_t)lr * 80 + (uint32_t)lq * 16;
        STS128(adst, hi[0], hi[1], hi[2], hi[3]);

        CP_WAIT0();
        __syncthreads();

        if (t + 1 < NKT) {
            int k0n = (t + 1) * 32;
            if (avalid) {
                const float4* p = (const float4*)(aptr + k0n);
                *(float4*)(fA)     = p[0];
                *(float4*)(fA + 4) = p[1];
            }
            uint32_t nbase = sb + (uint32_t)((t + 1) & 1) * STAGE_B;
            #pragma unroll
            for (int i = 0; i < 2; i++) {
                int r = br0 + i * 64;
                uint32_t d = nbase + OFF_BHI + (uint32_t)r * 80 + bpart;
                CP16(d, (const char*)(g_bhi + (size_t)r * KIN + k0n) + bpart);
                CP16(d + (OFF_BLO - OFF_BHI),
                     (const char*)(g_blo + (size_t)r * KIN + k0n) + bpart);
            }
            CP_COMMIT();
        }

        #pragma unroll
        for (int kk = 0; kk < 2; kk++) {
            int kc = kk * 16 + ((lane >> 4) << 3);
            int arow = wm * 32 + (lane & 15);
            uint32_t ah[2][4];
            #pragma unroll
            for (int mi = 0; mi < 2; mi++) {
                uint32_t addr = base + (uint32_t)((arow + mi * 16) * PAD + kc) * 2;
                ldsm4(ah[mi], addr);
            }
            int brow = wn * 32 + (lane & 15);
            uint32_t bh[4][2], bl[4][2];
            #pragma unroll
            for (int np = 0; np < 2; np++) {
                uint32_t r[4];
                uint32_t addr = base + OFF_BHI + (uint32_t)((brow + np * 16) * PAD + kc) * 2;
                ldsm4(r, addr);
                bh[2 * np][0] = r[0]; bh[2 * np][1] = r[2];
                bh[2 * np + 1][0] = r[1]; bh[2 * np + 1][1] = r[3];
                ldsm4(r, addr + (OFF_BLO - OFF_BHI));
                bl[2 * np][0] = r[0]; bl[2 * np][1] = r[2];
                bl[2 * np + 1][0] = r[1]; bl[2 * np + 1][1] = r[3];
            }
            #pragma unroll
            for (int mi = 0; mi < 2; mi++)
                #pragma unroll
                for (int ni = 0; ni < 4; ni++) {
                    mma_f16(acc[mi][ni], ah[mi], bh[ni]);
                    mma_f16(acc[mi][ni], ah[mi], bl[ni]);
                }
        }
    }

    int r = lane >> 2, c = (lane & 3) * 2;
    #pragma unroll
    for (int mi = 0; mi < 2; mi++) {
        int m0 = row0 + wm * 32 + mi * 16 + r;
        #pragma unroll
        for (int ni = 0; ni < 4; ni++) {
            int n = wn * 32 + ni * 8 + c;
            if (m0 < M) {
                __half2 v = __floats2half2_rn(acc[mi][ni][0], acc[mi][ni][1]);
                *(__half2*)&g_hh[(size_t)m0 * NH + n] = v;
            }
            if (m0 + 8 < M) {
                __half2 v = __floats2half2_rn(acc[mi][ni][2], acc[mi][ni][3]);
                *(__half2*)&g_hh[(size_t)(m0 + 8) * NH + n] = v;
            }
        }
    }
}

// ------- fused gather + finalize: half-warp per node (+ deg reset for next iter) -------
__global__ void gather_kernel(const int* __restrict__ perm,
                              const float* __restrict__ b,
                              const float* __restrict__ alpha,
                              float* __restrict__ out, int N) {
    size_t gid = (size_t)blockIdx.x * blockDim.x + threadIdx.x;
    int node = (int)(gid >> 4);
    int sl   = (int)(gid & 15);
    if (node >= N) return;

    int start = g_row[node];
    int cnt   = g_deg_in[node];
    int foff  = sl * 8;

    float acc1[8], acc2[8];
    #pragma unroll
    for (int q = 0; q < 8; q++) { acc1[q] = 0.f; acc2[q] = 0.f; }

    for (int i = 0; i < cnt; i++) {
        int s  = __ldg(&g_csrc[start + i]);
        int sp = __ldg(&perm[s]);
        float sc = __ldg(&g_norm_out[s]);
        uint4 u1 = *(const uint4*)(g_hh + (size_t)s  * NH + foff);
        uint4 u2 = *(const uint4*)(g_hh + (size_t)sp * NH + foff);
        float2 p;
        p = __half22float2(*(__half2*)&u1.x); acc1[0] = fmaf(p.x, sc, acc1[0]); acc1[1] = fmaf(p.y, sc, acc1[1]);
        p = __half22float2(*(__half2*)&u1.y); acc1[2] = fmaf(p.x, sc, acc1[2]); acc1[3] = fmaf(p.y, sc, acc1[3]);
        p = __half22float2(*(__half2*)&u1.z); acc1[4] = fmaf(p.x, sc, acc1[4]); acc1[5] = fmaf(p.y, sc, acc1[5]);
        p = __half22float2(*(__half2*)&u1.w); acc1[6] = fmaf(p.x, sc, acc1[6]); acc1[7] = fmaf(p.y, sc, acc1[7]);
        p = __half22float2(*(__half2*)&u2.x); acc2[0] = fmaf(p.x, sc, acc2[0]); acc2[1] = fmaf(p.y, sc, acc2[1]);
        p = __half22float2(*(__half2*)&u2.y); acc2[2] = fmaf(p.x, sc, acc2[2]); acc2[3] = fmaf(p.y, sc, acc2[3]);
        p = __half22float2(*(__half2*)&u2.z); acc2[4] = fmaf(p.x, sc, acc2[4]); acc2[5] = fmaf(p.y, sc, acc2[5]);
        p = __half22float2(*(__half2*)&u2.w); acc2[6] = fmaf(p.x, sc, acc2[6]); acc2[7] = fmaf(p.y, sc, acc2[7]);
    }

    float nin = g_norm_in[node];
    float bb[8], al[8], ws[8];
    *(float4*)(bb)     = *(const float4*)(b      + foff);
    *(float4*)(bb + 4) = *(const float4*)(b      + foff + 4);
    *(float4*)(al)     = *(const float4*)(alpha  + foff);
    *(float4*)(al + 4) = *(const float4*)(alpha  + foff + 4);
    *(float4*)(ws)     = *(const float4*)(g_wsum + foff);
    *(float4*)(ws + 4) = *(const float4*)(g_wsum + foff + 4);

    float r1 = 0.f, r2 = 0.f;
    #pragma unroll
    for (int q = 0; q < 8; q++) {
        float v1 = acc1[q] * nin + bb[q];
        v1 = (v1 >= 0.f) ? v1 : al[q] * v1;
        r1 = fmaf(v1, ws[q], r1);
        float v2 = acc2[q] * nin + bb[q];
        v2 = (v2 >= 0.f) ? v2 : al[q] * v2;
        r2 = fmaf(v2, ws[q], r2);
    }

    #pragma unroll
    for (int o = 8; o > 0; o >>= 1) {
        r1 += __shfl_xor_sync(0xFFFFFFFFu, r1, o);
        r2 += __shfl_xor_sync(0xFFFFFFFFu, r2, o);
    }
    if (sl == 0) {
        float bs = g_bsum;
        out[node]     = r1 + bs;
        out[N + node] = r2 + bs;
        g_deg_in[node]  = 0;   // reset for next graph replay
        g_deg_out[node] = 0;
    }
}

// ---------------- launch: 5 kernels ----------------
extern "C" void kernel_launch(void* const* d_in, const int* in_sizes, int n_in,
                              void* d_out, int out_size) {
    const float* x     = (const float*)d_in[0];
    const int*   src   = (const int*)  d_in[1];
    const int*   dst   = (const int*)  d_in[2];
    const int*   perm  = (const int*)  d_in[3];
    const float* W     = (const float*)d_in[4];
    const float* b     = (const float*)d_in[5];
    const float* alpha = (const float*)d_in[6];
    const float* mlpW  = (const float*)d_in[7];
    const float* mlpb  = (const float*)d_in[8];
    float* out = (float*)d_out;

    int E = in_sizes[1];
    int N = in_sizes[3];
    if (N > N_MAX || E > E_MAX) return;

    int nb = (N + SCAN_B - 1) / SCAN_B;

    cudaFuncSetAttribute(gemm_mma_kernel,
                         cudaFuncAttributeMaxDynamicSharedMemorySize, GEMM_SMEM);

    degprep_kernel<<<(E + 255) / 256, 256>>>(src, dst, E, W, mlpW, mlpb);
    gemm_mma_kernel<<<(N + 63) / 64, 256, GEMM_SMEM>>>(x, N);
    scan_kernel   <<<nb, SCAN_B>>>(N);
    fill_kernel   <<<(E + 255) / 256, 256>>>(src, dst, E, nb);

    size_t gthreads = (size_t)N * 16;
    gather_kernel<<<(unsigned)((gthreads + 255) / 256), 256>>>(perm, b, alpha, out, N);
}

// round 16
// speedup vs baseline: 1.1150x; 1.0121x over previous
#include <cuda_runtime.h>
#include <cuda_bf16.h>
#include <cuda_fp16.h>
#include <cstdint>

#define KIN 512
#define NH  128
#define N_MAX 100000
#define E_MAX 1600000
#define SCAN_B 256
#define NB_MAX ((N_MAX + SCAN_B - 1) / SCAN_B)

// ---------------- scratch (no allocations allowed; all start zeroed) ----------------
__device__ __half g_hh[(size_t)N_MAX * NH];    // h = x @ W  (fp16)
__device__ int   g_deg_in [N_MAX];             // zeroed by gather tail each iteration
__device__ int   g_deg_out[N_MAX];             // zeroed by gather tail each iteration
__device__ float g_norm_out[N_MAX];
__device__ float g_norm_in [N_MAX];
__device__ int   g_row  [N_MAX];
__device__ int   g_rank [E_MAX];               // edge's rank within its dst
__device__ int   g_csrc [E_MAX];
__device__ unsigned long long g_state[NB_MAX]; // zeroed by fill tail each iteration
__device__ float g_wsum[NH];
__device__ float g_bsum;
__device__ __half g_bhi[NH * KIN];             // W^T fp16 hi : [n][k]
__device__ __half g_blo[NH * KIN];             // W^T fp16 lo : [n][k]

// ================= helpers =================
__device__ __forceinline__ uint32_t smem_u32(const void* p) {
    uint32_t a;
    asm("{ .reg .u64 t; cvta.to.shared.u64 t, %1; cvt.u32.u64 %0, t; }"
        : "=r"(a) : "l"(p));
    return a;
}

__device__ __forceinline__ void ldsm4(uint32_t* r, uint32_t addr) {
    asm volatile("ldmatrix.sync.aligned.m8n8.x4.shared.b16 {%0,%1,%2,%3}, [%4];"
                 : "=r"(r[0]), "=r"(r[1]), "=r"(r[2]), "=r"(r[3]) : "r"(addr));
}

__device__ __forceinline__ void mma_f16(float* d, const uint32_t* a, const uint32_t* b) {
    asm volatile(
        "mma.sync.aligned.m16n8k16.row.col.f32.f16.f16.f32 "
        "{%0,%1,%2,%3}, {%4,%5,%6,%7}, {%8,%9}, {%0,%1,%2,%3};"
        : "+f"(d[0]), "+f"(d[1]), "+f"(d[2]), "+f"(d[3])
        : "r"(a[0]), "r"(a[1]), "r"(a[2]), "r"(a[3]), "r"(b[0]), "r"(b[1]));
}

#define CP16(dst, src) \
    asm volatile("cp.async.cg.shared.global [%0], [%1], 16;" :: "r"(dst), "l"(src))
#define CP_COMMIT() asm volatile("cp.async.commit_group;" ::: "memory")
#define CP_WAIT0()  asm volatile("cp.async.wait_group 0;"  ::: "memory")
#define STS128(a, r0, r1, r2, r3) \
    asm volatile("st.shared.v4.b32 [%0], {%1,%2,%3,%4};" \
                 :: "r"(a), "r"(r0), "r"(r1), "r"(r2), "r"(r3))

// ------- fused: degree atomics (+rank capture) + W split + wsum + bsum -------
__global__ void degprep_kernel(const int* __restrict__ src,
                               const int* __restrict__ dst, int E,
                               const float* __restrict__ W,
                               const float* __restrict__ mlpW,
                               const float* __restrict__ mlpb) {
    int i = blockIdx.x * blockDim.x + threadIdx.x;
    if (i < KIN * NH) {
        int k = i >> 7, n = i & 127;
        float v = W[i];
        __half h = __float2half_rn(v);
        g_bhi[n * KIN + k] = h;
        g_blo[n * KIN + k] = __float2half_rn(v - __half2float(h));
    }
    if (blockIdx.x < NH && threadIdx.x < 32) {
        int lane = threadIdx.x;
        float s = 0.f;
        #pragma unroll
        for (int k = lane; k < NH; k += 32) s += mlpW[blockIdx.x * NH + k];
        #pragma unroll
        for (int o = 16; o > 0; o >>= 1) s += __shfl_xor_sync(0xFFFFFFFFu, s, o);
        if (lane == 0) g_wsum[blockIdx.x] = s;
    }
    if (blockIdx.x == NH && threadIdx.x < 32) {
        int lane = threadIdx.x;
        float s = 0.f;
        #pragma unroll
        for (int k = lane; k < NH; k += 32) s += mlpb[k];
        #pragma unroll
        for (int o = 16; o > 0; o >>= 1) s += __shfl_xor_sync(0xFFFFFFFFu, s, o);
        if (lane == 0) g_bsum = s;
    }
    if (i < E) {
        atomicAdd(&g_deg_out[src[i]], 1);
        g_rank[i] = atomicAdd(&g_deg_in[dst[i]], 1);   // rank within dst, free
    }
}

// ------- single-pass scan (warp-shuffle + decoupled lookback) + norm -------
__global__ void scan_kernel(int N) {
    __shared__ int swsum[8];
    __shared__ int s_base;
    int t = threadIdx.x;
    int b = blockIdx.x;
    int i = b * SCAN_B + t;
    int lane = t & 31, widx = t >> 5;
    int v = (i < N) ? g_deg_in[i] : 0;

    // warp inclusive scan
    int acc = v;
    #pragma unroll
    for (int o = 1; o < 32; o <<= 1) {
        int n = __shfl_up_sync(0xFFFFFFFFu, acc, o);
        if (lane >= o) acc += n;
    }
    if (lane == 31) swsum[widx] = acc;
    __syncthreads();

    if (widx == 0) {
        int wv = (lane < 8) ? swsum[lane] : 0;
        #pragma unroll
        for (int o = 1; o < 8; o <<= 1) {
            int n = __shfl_up_sync(0xFFFFFFFFu, wv, o);
            if (lane >= o) wv += n;
        }
        if (lane < 8) swsum[lane] = wv;
    }
    __syncthreads();

    int woff = (widx > 0) ? swsum[widx - 1] : 0;
    acc += woff;                       // block-inclusive
    int tot = swsum[7];

    if (t == 0) {
        unsigned long long st =
            ((unsigned long long)(b == 0 ? 2u : 1u) << 32) | (unsigned)tot;
        atomicExch(&g_state[b], st);
        if (b == 0) s_base = 0;
    }

    if (b > 0 && t < 32) {
        int base = 0;
        int idx = b - 1;
        for (;;) {
            int j = idx - t;
            int f, val;
            if (j >= 0) {
                unsigned long long st;
                do { st = atomicAdd(&g_state[j], 0ULL); } while ((st >> 32) == 0);
                f = (int)(st >> 32);
                val = (int)(st & 0xffffffffULL);
            } else { f = 2; val = 0; }
            unsigned incmask = __ballot_sync(0xffffffffu, f == 2);
            int firstinc = __ffs(incmask) - 1;
            int contrib;
            if (incmask)
                contrib = (t <= firstinc) ? val : 0;
            else
                contrib = val;
            #pragma unroll
            for (int o = 16; o > 0; o >>= 1)
                contrib += __shfl_xor_sync(0xffffffffu, contrib, o);
            base += contrib;
            if (incmask) break;
            idx -= 32;
        }
        if (t == 0) {
            s_base = base;
            unsigned long long st = (2ULL << 32) | (unsigned)(base + tot);
            atomicExch(&g_state[b], st);
        }
    }
    __syncthreads();

    if (i < N) {
        int r = s_base + acc - v;      // exclusive
        g_row[i] = r;
        g_norm_out[i] = rsqrtf(fmaxf((float)g_deg_out[i], 1.0f));
        g_norm_in[i]  = rsqrtf(fmaxf((float)g_deg_in[i],  1.0f));
    }
}

// ---------------- CSR fill: ATOMIC-FREE (row + precomputed rank) ----------------
__global__ void fill_kernel(const int* __restrict__ src,
                            const int* __restrict__ dst, int E, int nb) {
    int i = blockIdx.x * blockDim.x + threadIdx.x;
    if (i < nb) g_state[i] = 0ULL;     // scan fully done; safe to reset
    if (i < E) {
        int d = dst[i];
        g_csrc[__ldg(&g_row[d]) + g_rank[i]] = src[i];
    }
}

// ============ fp16 HMMA GEMM (A single, W split), 64x128 tile — R10 config (protected) ============
#define PAD 40           // fp16 elems per SMEM row (80B)
#define OFF_BHI 5120     // A: 64 rows x 80B
#define OFF_BLO 15360    // Bhi: 128 rows x 80B
#define STAGE_B 25600
#define GEMM_SMEM (2 * STAGE_B)
#define NKT (KIN / 32)   // 16 K-tiles

__global__ __launch_bounds__(256) void gemm_mma_kernel(const float* __restrict__ A, int M) {
    extern __shared__ char smem[];
    uint32_t sb = smem_u32(smem);

    int tid = threadIdx.x;
    int lane = tid & 31, wid = tid >> 5;
    int wm = wid & 1;       // 2 m-slabs of 32
    int wn = wid >> 1;      // 4 n-slabs of 32
    int row0 = blockIdx.x * 64;

    float acc[2][4][4];
    #pragma unroll
    for (int i = 0; i < 2; i++)
        #pragma unroll
        for (int j = 0; j < 4; j++)
            #pragma unroll
            for (int q = 0; q < 4; q++) acc[i][j][q] = 0.f;

    int lr = tid >> 2;           // row within A tile (0..63)
    int lq = tid & 3;            // 8-float chunk (0..3)
    bool avalid = (row0 + lr) < M;
    const float* aptr = A + (size_t)(row0 + lr) * KIN + lq * 8;
    int br0 = tid >> 2;          // B row base (0..63)
    int bpart = (tid & 3) * 16;  // 16B part within 64B row

    float fA[8];
    if (avalid) {
        const float4* p = (const float4*)aptr;
        *(float4*)(fA)     = p[0];
        *(float4*)(fA + 4) = p[1];
    } else {
        #pragma unroll
        for (int i = 0; i < 8; i++) fA[i] = 0.f;
    }
    #pragma unroll
    for (int i = 0; i < 2; i++) {
        int r = br0 + i * 64;
        uint32_t d = sb + OFF_BHI + (uint32_t)r * 80 + bpart;
        CP16(d, (const char*)(g_bhi + (size_t)r * KIN) + bpart);
        CP16(d + (OFF_BLO - OFF_BHI), (const char*)(g_blo + (size_t)r * KIN) + bpart);
    }
    CP_COMMIT();

    #pragma unroll 1
    for (int t = 0; t < NKT; t++) {
        uint32_t base = sb + (uint32_t)(t & 1) * STAGE_B;

        uint32_t hi[4];
        #pragma unroll
        for (int p = 0; p < 4; p++) {
            __half2 h2 = __floats2half2_rn(fA[2 * p], fA[2 * p + 1]);
            hi[p] = *(uint32_t*)&h2;
        }
        uint32_t adst = base + (uint32_t)lr * 80 + (uint32_t)lq * 16;
        STS128(adst, hi[0], hi[1], hi[2], hi[3]);

        CP_WAIT0();
        __syncthreads();

        if (t + 1 < NKT) {
            int k0n = (t + 1) * 32;
            if (avalid) {
                const float4* p = (const float4*)(aptr + k0n);
                *(float4*)(fA)     = p[0];
                *(float4*)(fA + 4) = p[1];
            }
            uint32_t nbase = sb + (uint32_t)((t + 1) & 1) * STAGE_B;
            #pragma unroll
            for (int i = 0; i < 2; i++) {
                int r = br0 + i * 64;
                uint32_t d = nbase + OFF_BHI + (uint32_t)r * 80 + bpart;
                CP16(d, (const char*)(g_bhi + (size_t)r * KIN + k0n) + bpart);
                CP16(d + (OFF_BLO - OFF_BHI),
                     (const char*)(g_blo + (size_t)r * KIN + k0n) + bpart);
            }
            CP_COMMIT();
        }

        #pragma unroll
        for (int kk = 0; kk < 2; kk++) {
            int kc = kk * 16 + ((lane >> 4) << 3);
            int arow = wm * 32 + (lane & 15);
            uint32_t ah[2][4];
            #pragma unroll
            for (int mi = 0; mi < 2; mi++) {
                uint32_t addr = base + (uint32_t)((arow + mi * 16) * PAD + kc) * 2;
                ldsm4(ah[mi], addr);
            }
            int brow = wn * 32 + (lane & 15);
            uint32_t bh[4][2], bl[4][2];
            #pragma unroll
            for (int np = 0; np < 2; np++) {
                uint32_t r[4];
                uint32_t addr = base + OFF_BHI + (uint32_t)((brow + np * 16) * PAD + kc) * 2;
                ldsm4(r, addr);
                bh[2 * np][0] = r[0]; bh[2 * np][1] = r[2];
                bh[2 * np + 1][0] = r[1]; bh[2 * np + 1][1] = r[3];
                ldsm4(r, addr + (OFF_BLO - OFF_BHI));
                bl[2 * np][0] = r[0]; bl[2 * np][1] = r[2];
                bl[2 * np + 1][0] = r[1]; bl[2 * np + 1][1] = r[3];
            }
            #pragma unroll
            for (int mi = 0; mi < 2; mi++)
                #pragma unroll
                for (int ni = 0; ni < 4; ni++) {
                    mma_f16(acc[mi][ni], ah[mi], bh[ni]);
                    mma_f16(acc[mi][ni], ah[mi], bl[ni]);
                }
        }
    }

    int r = lane >> 2, c = (lane & 3) * 2;
    #pragma unroll
    for (int mi = 0; mi < 2; mi++) {
        int m0 = row0 + wm * 32 + mi * 16 + r;
        #pragma unroll
        for (int ni = 0; ni < 4; ni++) {
            int n = wn * 32 + ni * 8 + c;
            if (m0 < M) {
                __half2 v = __floats2half2_rn(acc[mi][ni][0], acc[mi][ni][1]);
                *(__half2*)&g_hh[(size_t)m0 * NH + n] = v;
            }
            if (m0 + 8 < M) {
                __half2 v = __floats2half2_rn(acc[mi][ni][2], acc[mi][ni][3]);
                *(__half2*)&g_hh[(size_t)(m0 + 8) * NH + n] = v;
            }
        }
    }
}

// ------- fused gather + finalize: half-warp per node (+ deg reset for next iter) -------
__global__ void gather_kernel(const int* __restrict__ perm,
                              const float* __restrict__ b,
                              const float* __restrict__ alpha,
                              float* __restrict__ out, int N) {
    size_t gid = (size_t)blockIdx.x * blockDim.x + threadIdx.x;
    int node = (int)(gid >> 4);
    int sl   = (int)(gid & 15);
    if (node >= N) return;

    int start = g_row[node];
    int cnt   = g_deg_in[node];
    int foff  = sl * 8;

    float acc1[8], acc2[8];
    #pragma unroll
    for (int q = 0; q < 8; q++) { acc1[q] = 0.f; acc2[q] = 0.f; }

    for (int i = 0; i < cnt; i++) {
        int s  = __ldg(&g_csrc[start + i]);
        int sp = __ldg(&perm[s]);
        float sc = __ldg(&g_norm_out[s]);
        uint4 u1 = *(const uint4*)(g_hh + (size_t)s  * NH + foff);
        uint4 u2 = *(const uint4*)(g_hh + (size_t)sp * NH + foff);
        float2 p;
        p = __half22float2(*(__half2*)&u1.x); acc1[0] = fmaf(p.x, sc, acc1[0]); acc1[1] = fmaf(p.y, sc, acc1[1]);
        p = __half22float2(*(__half2*)&u1.y); acc1[2] = fmaf(p.x, sc, acc1[2]); acc1[3] = fmaf(p.y, sc, acc1[3]);
        p = __half22float2(*(__half2*)&u1.z); acc1[4] = fmaf(p.x, sc, acc1[4]); acc1[5] = fmaf(p.y, sc, acc1[5]);
        p = __half22float2(*(__half2*)&u1.w); acc1[6] = fmaf(p.x, sc, acc1[6]); acc1[7] = fmaf(p.y, sc, acc1[7]);
        p = __half22float2(*(__half2*)&u2.x); acc2[0] = fmaf(p.x, sc, acc2[0]); acc2[1] = fmaf(p.y, sc, acc2[1]);
        p = __half22float2(*(__half2*)&u2.y); acc2[2] = fmaf(p.x, sc, acc2[2]); acc2[3] = fmaf(p.y, sc, acc2[3]);
        p = __half22float2(*(__half2*)&u2.z); acc2[4] = fmaf(p.x, sc, acc2[4]); acc2[5] = fmaf(p.y, sc, acc2[5]);
        p = __half22float2(*(__half2*)&u2.w); acc2[6] = fmaf(p.x, sc, acc2[6]); acc2[7] = fmaf(p.y, sc, acc2[7]);
    }

    float nin = g_norm_in[node];
    float bb[8], al[8], ws[8];
    *(float4*)(bb)     = *(const float4*)(b      + foff);
    *(float4*)(bb + 4) = *(const float4*)(b      + foff + 4);
    *(float4*)(al)     = *(const float4*)(alpha  + foff);
    *(float4*)(al + 4) = *(const float4*)(alpha  + foff + 4);
    *(float4*)(ws)     = *(const float4*)(g_wsum + foff);
    *(float4*)(ws + 4) = *(const float4*)(g_wsum + foff + 4);

    float r1 = 0.f, r2 = 0.f;
    #pragma unroll
    for (int q = 0; q < 8; q++) {
        float v1 = acc1[q] * nin + bb[q];
        v1 = (v1 >= 0.f) ? v1 : al[q] * v1;
        r1 = fmaf(v1, ws[q], r1);
        float v2 = acc2[q] * nin + bb[q];
        v2 = (v2 >= 0.f) ? v2 : al[q] * v2;
        r2 = fmaf(v2, ws[q], r2);
    }

    #pragma unroll
    for (int o = 8; o > 0; o >>= 1) {
        r1 += __shfl_xor_sync(0xFFFFFFFFu, r1, o);
        r2 += __shfl_xor_sync(0xFFFFFFFFu, r2, o);
    }
    if (sl == 0) {
        float bs = g_bsum;
        out[node]     = r1 + bs;
        out[N + node] = r2 + bs;
        g_deg_in[node]  = 0;   // reset for next graph replay
        g_deg_out[node] = 0;
    }
}

// ---------------- launch: 5 kernels ----------------
extern "C" void kernel_launch(void* const* d_in, const int* in_sizes, int n_in,
                              void* d_out, int out_size) {
    const float* x     = (const float*)d_in[0];
    const int*   src   = (const int*)  d_in[1];
    const int*   dst   = (const int*)  d_in[2];
    const int*   perm  = (const int*)  d_in[3];
    const float* W     = (const float*)d_in[4];
    const float* b     = (const float*)d_in[5];
    const float* alpha = (const float*)d_in[6];
    const float* mlpW  = (const float*)d_in[7];
    const float* mlpb  = (const float*)d_in[8];
    float* out = (float*)d_out;

    int E = in_sizes[1];
    int N = in_sizes[3];
    if (N > N_MAX || E > E_MAX) return;

    int nb = (N + SCAN_B - 1) / SCAN_B;

    cudaFuncSetAttribute(gemm_mma_kernel,
                         cudaFuncAttributeMaxDynamicSharedMemorySize, GEMM_SMEM);

    degprep_kernel<<<(E + 255) / 256, 256>>>(src, dst, E, W, mlpW, mlpb);
    gemm_mma_kernel<<<(N + 63) / 64, 256, GEMM_SMEM>>>(x, N);
    scan_kernel   <<<nb, SCAN_B>>>(N);
    fill_kernel   <<<(E + 255) / 256, 256>>>(src, dst, E, nb);

    size_t gthreads = (size_t)N * 16;
    gather_kernel<<<(unsigned)((gthreads + 255) / 256), 256>>>(perm, b, alpha, out, N);
}

// round 17
// speedup vs baseline: 1.1174x; 1.0021x over previous
#include <cuda_runtime.h>
#include <cuda_bf16.h>
#include <cuda_fp16.h>
#include <cstdint>

#define KIN 512
#define NH  128
#define N_MAX 100000
#define E_MAX 1600000
#define SCAN_B 256
#define NB_MAX ((N_MAX + SCAN_B - 1) / SCAN_B)

// ---------------- scratch (no allocations allowed; all start zeroed) ----------------
__device__ __half g_hh[(size_t)N_MAX * NH];    // h = x @ W  (fp16)
__device__ int   g_deg_in [N_MAX];             // zeroed by gather tail each iteration
__device__ int   g_deg_out[N_MAX];             // zeroed by gather tail each iteration
__device__ float g_norm_out[N_MAX];
__device__ float g_norm_in [N_MAX];
__device__ int   g_row  [N_MAX];
__device__ int   g_rank [E_MAX];               // edge's rank within its dst
__device__ int   g_csrc [E_MAX];
__device__ unsigned long long g_state[NB_MAX]; // zeroed by fill tail each iteration
__device__ float g_wsum[NH];
__device__ float g_bsum;
__device__ __half g_bhi[NH * KIN];             // W^T fp16 hi : [n][k]
__device__ __half g_blo[NH * KIN];             // W^T fp16 lo : [n][k]

// ================= helpers =================
__device__ __forceinline__ uint32_t smem_u32(const void* p) {
    uint32_t a;
    asm("{ .reg .u64 t; cvta.to.shared.u64 t, %1; cvt.u32.u64 %0, t; }"
        : "=r"(a) : "l"(p));
    return a;
}

__device__ __forceinline__ void ldsm4(uint32_t* r, uint32_t addr) {
    asm volatile("ldmatrix.sync.aligned.m8n8.x4.shared.b16 {%0,%1,%2,%3}, [%4];"
                 : "=r"(r[0]), "=r"(r[1]), "=r"(r[2]), "=r"(r[3]) : "r"(addr));
}

__device__ __forceinline__ void mma_f16(float* d, const uint32_t* a, const uint32_t* b) {
    asm volatile(
        "mma.sync.aligned.m16n8k16.row.col.f32.f16.f16.f32 "
        "{%0,%1,%2,%3}, {%4,%5,%6,%7}, {%8,%9}, {%0,%1,%2,%3};"
        : "+f"(d[0]), "+f"(d[1]), "+f"(d[2]), "+f"(d[3])
        : "r"(a[0]), "r"(a[1]), "r"(a[2]), "r"(a[3]), "r"(b[0]), "r"(b[1]));
}

#define CP16(dst, src) \
    asm volatile("cp.async.cg.shared.global [%0], [%1], 16;" :: "r"(dst), "l"(src))
#define CP_COMMIT() asm volatile("cp.async.commit_group;" ::: "memory")
#define CP_WAIT0()  asm volatile("cp.async.wait_group 0;"  ::: "memory")
#define STS128(a, r0, r1, r2, r3) \
    asm volatile("st.shared.v4.b32 [%0], {%1,%2,%3,%4};" \
                 :: "r"(a), "r"(r0), "r"(r1), "r"(r2), "r"(r3))

// ------- fused: degree atomics (+rank, 2 edges/thread) + W split + wsum + bsum -------
__global__ void degprep_kernel(const int* __restrict__ src,
                               const int* __restrict__ dst, int E,
                               const float* __restrict__ W,
                               const float* __restrict__ mlpW,
                               const float* __restrict__ mlpb) {
    int i = blockIdx.x * blockDim.x + threadIdx.x;
    if (i < KIN * NH) {
        int k = i >> 7, n = i & 127;
        float v = W[i];
        __half h = __float2half_rn(v);
        g_bhi[n * KIN + k] = h;
        g_blo[n * KIN + k] = __float2half_rn(v - __half2float(h));
    }
    if (blockIdx.x < NH && threadIdx.x < 32) {
        int lane = threadIdx.x;
        float s = 0.f;
        #pragma unroll
        for (int k = lane; k < NH; k += 32) s += mlpW[blockIdx.x * NH + k];
        #pragma unroll
        for (int o = 16; o > 0; o >>= 1) s += __shfl_xor_sync(0xFFFFFFFFu, s, o);
        if (lane == 0) g_wsum[blockIdx.x] = s;
    }
    if (blockIdx.x == NH && threadIdx.x < 32) {
        int lane = threadIdx.x;
        float s = 0.f;
        #pragma unroll
        for (int k = lane; k < NH; k += 32) s += mlpb[k];
        #pragma unroll
        for (int o = 16; o > 0; o >>= 1) s += __shfl_xor_sync(0xFFFFFFFFu, s, o);
        if (lane == 0) g_bsum = s;
    }
    int e0 = i * 2;
    if (e0 + 1 < E) {
        int2 s2 = *(const int2*)(src + e0);
        int2 d2 = *(const int2*)(dst + e0);
        atomicAdd(&g_deg_out[s2.x], 1);
        atomicAdd(&g_deg_out[s2.y], 1);
        int r0 = atomicAdd(&g_deg_in[d2.x], 1);
        int r1 = atomicAdd(&g_deg_in[d2.y], 1);
        *(int2*)(g_rank + e0) = make_int2(r0, r1);
    } else if (e0 < E) {
        atomicAdd(&g_deg_out[src[e0]], 1);
        g_rank[e0] = atomicAdd(&g_deg_in[dst[e0]], 1);
    }
}

// ------- single-pass scan (warp-shuffle + decoupled lookback) + norm -------
__global__ void scan_kernel(int N) {
    __shared__ int swsum[8];
    __shared__ int s_base;
    int t = threadIdx.x;
    int b = blockIdx.x;
    int i = b * SCAN_B + t;
    int lane = t & 31, widx = t >> 5;
    int v = (i < N) ? g_deg_in[i] : 0;

    // warp inclusive scan
    int acc = v;
    #pragma unroll
    for (int o = 1; o < 32; o <<= 1) {
        int n = __shfl_up_sync(0xFFFFFFFFu, acc, o);
        if (lane >= o) acc += n;
    }
    if (lane == 31) swsum[widx] = acc;
    __syncthreads();

    if (widx == 0) {
        int wv = (lane < 8) ? swsum[lane] : 0;
        #pragma unroll
        for (int o = 1; o < 8; o <<= 1) {
            int n = __shfl_up_sync(0xFFFFFFFFu, wv, o);
            if (lane >= o) wv += n;
        }
        if (lane < 8) swsum[lane] = wv;
    }
    __syncthreads();

    int woff = (widx > 0) ? swsum[widx - 1] : 0;
    acc += woff;                       // block-inclusive
    int tot = swsum[7];

    if (t == 0) {
        unsigned long long st =
            ((unsigned long long)(b == 0 ? 2u : 1u) << 32) | (unsigned)tot;
        atomicExch(&g_state[b], st);
        if (b == 0) s_base = 0;
    }

    if (b > 0 && t < 32) {
        int base = 0;
        int idx = b - 1;
        for (;;) {
            int j = idx - t;
            int f, val;
            if (j >= 0) {
                unsigned long long st;
                do { st = atomicAdd(&g_state[j], 0ULL); } while ((st >> 32) == 0);
                f = (int)(st >> 32);
                val = (int)(st & 0xffffffffULL);
            } else { f = 2; val = 0; }
            unsigned incmask = __ballot_sync(0xffffffffu, f == 2);
            int firstinc = __ffs(incmask) - 1;
            int contrib;
            if (incmask)
                contrib = (t <= firstinc) ? val : 0;
            else
                contrib = val;
            #pragma unroll
            for (int o = 16; o > 0; o >>= 1)
                contrib += __shfl_xor_sync(0xffffffffu, contrib, o);
            base += contrib;
            if (incmask) break;
            idx -= 32;
        }
        if (t == 0) {
            s_base = base;
            unsigned long long st = (2ULL << 32) | (unsigned)(base + tot);
            atomicExch(&g_state[b], st);
        }
    }
    __syncthreads();

    if (i < N) {
        int r = s_base + acc - v;      // exclusive
        g_row[i] = r;
        g_norm_out[i] = rsqrtf(fmaxf((float)g_deg_out[i], 1.0f));
        g_norm_in[i]  = rsqrtf(fmaxf((float)g_deg_in[i],  1.0f));
    }
}

// ---------------- CSR fill: atomic-free, 2 edges/thread ----------------
__global__ void fill_kernel(const int* __restrict__ src,
                            const int* __restrict__ dst, int E, int nb) {
    int i = blockIdx.x * blockDim.x + threadIdx.x;
    if (i < nb) g_state[i] = 0ULL;     // scan fully done; safe to reset
    int e0 = i * 2;
    if (e0 + 1 < E) {
        int2 s2 = *(const int2*)(src + e0);
        int2 d2 = *(const int2*)(dst + e0);
        int2 r2 = *(const int2*)(g_rank + e0);
        g_csrc[__ldg(&g_row[d2.x]) + r2.x] = s2.x;
        g_csrc[__ldg(&g_row[d2.y]) + r2.y] = s2.y;
    } else if (e0 < E) {
        g_csrc[__ldg(&g_row[dst[e0]]) + g_rank[e0]] = src[e0];
    }
}

// ============ fp16 HMMA GEMM (A single, W split), 64x128 tile — R10 config (protected) ============
#define PAD 40           // fp16 elems per SMEM row (80B)
#define OFF_BHI 5120     // A: 64 rows x 80B
#define OFF_BLO 15360    // Bhi: 128 rows x 80B
#define STAGE_B 25600
#define GEMM_SMEM (2 * STAGE_B)
#define NKT (KIN / 32)   // 16 K-tiles

__global__ __launch_bounds__(256) void gemm_mma_kernel(const float* __restrict__ A, int M) {
    extern __shared__ char smem[];
    uint32_t sb = smem_u32(smem);

    int tid = threadIdx.x;
    int lane = tid & 31, wid = tid >> 5;
    int wm = wid & 1;       // 2 m-slabs of 32
    int wn = wid >> 1;      // 4 n-slabs of 32
    int row0 = blockIdx.x * 64;

    float acc[2][4][4];
    #pragma unroll
    for (int i = 0; i < 2; i++)
        #pragma unroll
        for (int j = 0; j < 4; j++)
            #pragma unroll
            for (int q = 0; q < 4; q++) acc[i][j][q] = 0.f;

    int lr = tid >> 2;           // row within A tile (0..63)
    int lq = tid & 3;            // 8-float chunk (0..3)
    bool avalid = (row0 + lr) < M;
    const float* aptr = A + (size_t)(row0 + lr) * KIN + lq * 8;
    int br0 = tid >> 2;          // B row base (0..63)
    int bpart = (tid & 3) * 16;  // 16B part within 64B row

    float fA[8];
    if (avalid) {
        const float4* p = (const float4*)aptr;
        *(float4*)(fA)     = p[0];
        *(float4*)(fA + 4) = p[1];
    } else {
        #pragma unroll
        for (int i = 0; i < 8; i++) fA[i] = 0.f;
    }
    #pragma unroll
    for (int i = 0; i < 2; i++) {
        int r = br0 + i * 64;
        uint32_t d = sb + OFF_BHI + (uint32_t)r * 80 + bpart;
        CP16(d, (const char*)(g_bhi + (size_t)r * KIN) + bpart);
        CP16(d + (OFF_BLO - OFF_BHI), (const char*)(g_blo + (size_t)r * KIN) + bpart);
    }
    CP_COMMIT();

    #pragma unroll 1
    for (int t = 0; t < NKT; t++) {
        uint32_t base = sb + (uint32_t)(t & 1) * STAGE_B;

        uint32_t hi[4];
        #pragma unroll
        for (int p = 0; p < 4; p++) {
            __half2 h2 = __floats2half2_rn(fA[2 * p], fA[2 * p + 1]);
            hi[p] = *(uint32_t*)&h2;
        }
        uint32_t adst = base + (uint32_t)lr * 80 + (uint32_t)lq * 16;
        STS128(adst, hi[0], hi[1], hi[2], hi[3]);

        CP_WAIT0();
        __syncthreads();

        if (t + 1 < NKT) {
            int k0n = (t + 1) * 32;
            if (avalid) {
                const float4* p = (const float4*)(aptr + k0n);
                *(float4*)(fA)     = p[0];
                *(float4*)(fA + 4) = p[1];
            }
            uint32_t nbase = sb + (uint32_t)((t + 1) & 1) * STAGE_B;
            #pragma unroll
            for (int i = 0; i < 2; i++) {
                int r = br0 + i * 64;
                uint32_t d = nbase + OFF_BHI + (uint32_t)r * 80 + bpart;
                CP16(d, (const char*)(g_bhi + (size_t)r * KIN + k0n) + bpart);
                CP16(d + (OFF_BLO - OFF_BHI),
                     (const char*)(g_blo + (size_t)r * KIN + k0n) + bpart);
            }
            CP_COMMIT();
        }

        #pragma unroll
        for (int kk = 0; kk < 2; kk++) {
            int kc = kk * 16 + ((lane >> 4) << 3);
            int arow = wm * 32 + (lane & 15);
            uint32_t ah[2][4];
            #pragma unroll
            for (int mi = 0; mi < 2; mi++) {
                uint32_t addr = base + (uint32_t)((arow + mi * 16) * PAD + kc) * 2;
                ldsm4(ah[mi], addr);
            }
            int brow = wn * 32 + (lane & 15);
            uint32_t bh[4][2], bl[4][2];
            #pragma unroll
            for (int np = 0; np < 2; np++) {
                uint32_t r[4];
                uint32_t addr = base + OFF_BHI + (uint32_t)((brow + np * 16) * PAD + kc) * 2;
                ldsm4(r, addr);
                bh[2 * np][0] = r[0]; bh[2 * np][1] = r[2];
                bh[2 * np + 1][0] = r[1]; bh[2 * np + 1][1] = r[3];
                ldsm4(r, addr + (OFF_BLO - OFF_BHI));
                bl[2 * np][0] = r[0]; bl[2 * np][1] = r[2];
                bl[2 * np + 1][0] = r[1]; bl[2 * np + 1][1] = r[3];
            }
            #pragma unroll
            for (int mi = 0; mi < 2; mi++)
                #pragma unroll
                for (int ni = 0; ni < 4; ni++) {
                    mma_f16(acc[mi][ni], ah[mi], bh[ni]);
                    mma_f16(acc[mi][ni], ah[mi], bl[ni]);
                }
        }
    }

    int r = lane >> 2, c = (lane & 3) * 2;
    #pragma unroll
    for (int mi = 0; mi < 2; mi++) {
        int m0 = row0 + wm * 32 + mi * 16 + r;
        #pragma unroll
        for (int ni = 0; ni < 4; ni++) {
            int n = wn * 32 + ni * 8 + c;
            if (m0 < M) {
                __half2 v = __floats2half2_rn(acc[mi][ni][0], acc[mi][ni][1]);
                *(__half2*)&g_hh[(size_t)m0 * NH + n] = v;
            }
            if (m0 + 8 < M) {
                __half2 v = __floats2half2_rn(acc[mi][ni][2], acc[mi][ni][3]);
                *(__half2*)&g_hh[(size_t)(m0 + 8) * NH + n] = v;
            }
        }
    }
}

// ------- fused gather + finalize: half-warp per node, index-chain pipelined -------
__global__ void gather_kernel(const int* __restrict__ perm,
                              const float* __restrict__ b,
                              const float* __restrict__ alpha,
                              float* __restrict__ out, int N) {
    size_t gid = (size_t)blockIdx.x * blockDim.x + threadIdx.x;
    int node = (int)(gid >> 4);
    int sl   = (int)(gid & 15);
    if (node >= N) return;

    int start = g_row[node];
    int cnt   = g_deg_in[node];
    int foff  = sl * 8;

    float acc1[8], acc2[8];
    #pragma unroll
    for (int q = 0; q < 8; q++) { acc1[q] = 0.f; acc2[q] = 0.f; }

    int s = 0, sp = 0;
    float sc = 0.f;
    if (cnt > 0) {
        s  = __ldg(&g_csrc[start]);
        sp = __ldg(&perm[s]);
        sc = __ldg(&g_norm_out[s]);
    }
    for (int i = 0; i < cnt; i++) {
        // issue current rows
        uint4 u1 = *(const uint4*)(g_hh + (size_t)s  * NH + foff);
        uint4 u2 = *(const uint4*)(g_hh + (size_t)sp * NH + foff);
        float scc = sc;
        // prefetch next index chain while rows are in flight
        if (i + 1 < cnt) {
            s  = __ldg(&g_csrc[start + i + 1]);
            sp = __ldg(&perm[s]);
            sc = __ldg(&g_norm_out[s]);
        }
        float2 p;
        p = __half22float2(*(__half2*)&u1.x); acc1[0] = fmaf(p.x, scc, acc1[0]); acc1[1] = fmaf(p.y, scc, acc1[1]);
        p = __half22float2(*(__half2*)&u1.y); acc1[2] = fmaf(p.x, scc, acc1[2]); acc1[3] = fmaf(p.y, scc, acc1[3]);
        p = __half22float2(*(__half2*)&u1.z); acc1[4] = fmaf(p.x, scc, acc1[4]); acc1[5] = fmaf(p.y, scc, acc1[5]);
        p = __half22float2(*(__half2*)&u1.w); acc1[6] = fmaf(p.x, scc, acc1[6]); acc1[7] = fmaf(p.y, scc, acc1[7]);
        p = __half22float2(*(__half2*)&u2.x); acc2[0] = fmaf(p.x, scc, acc2[0]); acc2[1] = fmaf(p.y, scc, acc2[1]);
        p = __half22float2(*(__half2*)&u2.y); acc2[2] = fmaf(p.x, scc, acc2[2]); acc2[3] = fmaf(p.y, scc, acc2[3]);
        p = __half22float2(*(__half2*)&u2.z); acc2[4] = fmaf(p.x, scc, acc2[4]); acc2[5] = fmaf(p.y, scc, acc2[5]);
        p = __half22float2(*(__half2*)&u2.w); acc2[6] = fmaf(p.x, scc, acc2[6]); acc2[7] = fmaf(p.y, scc, acc2[7]);
    }

    float nin = g_norm_in[node];
    float bb[8], al[8], ws[8];
    *(float4*)(bb)     = *(const float4*)(b      + foff);
    *(float4*)(bb + 4) = *(const float4*)(b      + foff + 4);
    *(float4*)(al)     = *(const float4*)(alpha  + foff);
    *(float4*)(al + 4) = *(const float4*)(alpha  + foff + 4);
    *(float4*)(ws)     = *(const float4*)(g_wsum + foff);
    *(float4*)(ws + 4) = *(const float4*)(g_wsum + foff + 4);

    float r1 = 0.f, r2 = 0.f;
    #pragma unroll
    for (int q = 0; q < 8; q++) {
        float v1 = acc1[q] * nin + bb[q];
        v1 = (v1 >= 0.f) ? v1 : al[q] * v1;
        r1 = fmaf(v1, ws[q], r1);
        float v2 = acc2[q] * nin + bb[q];
        v2 = (v2 >= 0.f) ? v2 : al[q] * v2;
        r2 = fmaf(v2, ws[q], r2);
    }

    #pragma unroll
    for (int o = 8; o > 0; o >>= 1) {
        r1 += __shfl_xor_sync(0xFFFFFFFFu, r1, o);
        r2 += __shfl_xor_sync(0xFFFFFFFFu, r2, o);
    }
    if (sl == 0) {
        float bs = g_bsum;
        out[node]     = r1 + bs;
        out[N + node] = r2 + bs;
        g_deg_in[node]  = 0;   // reset for next graph replay
        g_deg_out[node] = 0;
    }
}

// ---------------- launch: 5 kernels ----------------
extern "C" void kernel_launch(void* const* d_in, const int* in_sizes, int n_in,
                              void* d_out, int out_size) {
    const float* x     = (const float*)d_in[0];
    const int*   src   = (const int*)  d_in[1];
    const int*   dst   = (const int*)  d_in[2];
    const int*   perm  = (const int*)  d_in[3];
    const float* W     = (const float*)d_in[4];
    const float* b     = (const float*)d_in[5];
    const float* alpha = (const float*)d_in[6];
    const float* mlpW  = (const float*)d_in[7];
    const float* mlpb  = (const float*)d_in[8];
    float* out = (float*)d_out;

    int E = in_sizes[1];
    int N = in_sizes[3];
    if (N > N_MAX || E > E_MAX) return;

    int nb = (N + SCAN_B - 1) / SCAN_B;
    int half_e = (E + 1) / 2;
    // degprep/fill grids must still cover W-split / state-reset index ranges
    int dp_threads = half_e > KIN * NH ? half_e : KIN * NH;
    int dp_blocks = (dp_threads + 255) / 256;
    if (dp_blocks < NH + 1) dp_blocks = NH + 1;
    int fl_threads = half_e > nb ? half_e : nb;
    int fl_blocks = (fl_threads + 255) / 256;

    cudaFuncSetAttribute(gemm_mma_kernel,
                         cudaFuncAttributeMaxDynamicSharedMemorySize, GEMM_SMEM);

    degprep_kernel<<<dp_blocks, 256>>>(src, dst, E, W, mlpW, mlpb);
    gemm_mma_kernel<<<(N + 63) / 64, 256, GEMM_SMEM>>>(x, N);
    scan_kernel   <<<nb, SCAN_B>>>(N);
    fill_kernel   <<<fl_blocks, 256>>>(src, dst, E, nb);

    size_t gthreads = (size_t)N * 16;
    gather_kernel<<<(unsigned)((gthreads + 255) / 256), 256>>>(perm, b, alpha, out, N);
}